// round 4
// baseline (speedup 1.0000x reference)
#include <cuda_runtime.h>
#include <cstddef>

#define H       128
#define NPL     100000
#define NTR     200000
#define NAR     50000
#define NT      350000
#define OFF_TR  100000
#define OFF_AR  300000
#define EPT     500000
#define ETA     200000
#define LBL     100000
#define GRID    152

// ---------------- scratch ----------------
__device__ float g_x  [(size_t)NT * H];
__device__ float g_y  [(size_t)NT * H];
__device__ float g_agg[(size_t)NT * H];
__device__ float g_inv[NT];
__device__ int   g_deg[NT];

// ---------------- helpers ----------------
__device__ __forceinline__ void fma2(unsigned long long& d,
                                     unsigned long long a, unsigned long long b) {
    asm("fma.rn.f32x2 %0, %1, %2, %0;" : "+l"(d) : "l"(a), "l"(b));
}

union U64F2 { unsigned long long u; float2 f; };

__device__ __forceinline__ void red4(float* p, float4 v) {
    asm volatile("red.global.add.v4.f32 [%0], {%1,%2,%3,%4};"
                 :: "l"(p), "f"(v.x), "f"(v.y), "f"(v.z), "f"(v.w) : "memory");
}

__device__ __forceinline__ void cpa16(float* smem_dst, const float* gsrc) {
    unsigned ds = (unsigned)__cvta_generic_to_shared(smem_dst);
    asm volatile("cp.async.cg.shared.global [%0], [%1], 16;" :: "r"(ds), "l"(gsrc) : "memory");
}

// ---------------- embedding gather (pl / ar) ----------------
__global__ void k_embed(const int* __restrict__ ids, const float* __restrict__ table,
                        const float* __restrict__ trow, float* __restrict__ out, int n)
{
    int t = blockIdx.x * blockDim.x + threadIdx.x;
    if (t >= n * 32) return;
    int i = t >> 5, c = t & 31;
    float4 v  = ((const float4*)(table + (size_t)ids[i] * H))[c];
    float4 tv = ((const float4*)trow)[c];
    v.x += tv.x; v.y += tv.y; v.z += tv.z; v.w += tv.w;
    ((float4*)(out + (size_t)i * H))[c] = v;
}

// ---------------- degree count ----------------
__global__ void k_deg(const int* __restrict__ sp, const int* __restrict__ dp,
                      const int* __restrict__ st, const int* __restrict__ dt)
{
    int e = blockIdx.x * blockDim.x + threadIdx.x;
    if (e < EPT) {
        int s = sp[e], d = dp[e] + OFF_TR;
        atomicAdd(&g_deg[d], 1);
        atomicAdd(&g_deg[s], 1);
    } else if (e < EPT + ETA) {
        int i = e - EPT;
        int s = st[i] + OFF_TR, d = dt[i] + OFF_AR;
        atomicAdd(&g_deg[d], 1);
        atomicAdd(&g_deg[s], 1);
    }
}

__global__ void k_inv()
{
    int i = blockIdx.x * blockDim.x + threadIdx.x;
    if (i < NT) g_inv[i] = 1.0f / fmaxf((float)g_deg[i], 1.0f);
}

// ---------------- edge scatter ----------------
__global__ void k_scatter(const float* __restrict__ x,
                          const int* __restrict__ sp, const int* __restrict__ dp,
                          const int* __restrict__ st, const int* __restrict__ dt)
{
    long long t = (long long)blockIdx.x * blockDim.x + threadIdx.x;
    if (t >= (long long)(EPT + ETA) * 32) return;
    int e = (int)(t >> 5), c = (int)(t & 31);
    int a, b;
    if (e < EPT) { a = sp[e];          b = dp[e] + OFF_TR; }
    else { int i = e - EPT; a = st[i] + OFF_TR; b = dt[i] + OFF_AR; }
    float4 va = ((const float4*)(x + (size_t)a * H))[c];
    float4 vb = ((const float4*)(x + (size_t)b * H))[c];
    red4(g_agg + (size_t)b * H + 4 * c, va);
    red4(g_agg + (size_t)a * H + 4 * c, vb);
}

// ---------------- pipelined f32x2 linear ----------------
// 512 thr / 16 warps; tile = 32 nodes; chunk = (tile, part), K=128 per part.
// warp w: node group g=w>>2 (8 nodes), col quarter cq=(w&3)*32; lane owns 1 col.
// A-chunks double-buffered via cp.async (16KB each), prefetch distance 1.
// PARTS=2: partA -> accA (scaled by inv at epilogue), partB -> accB.
// GATHER: A rows from B-base via lrow/lcol. DOT: wp2-dot epilogue (logits).
template<int PARTS, bool SCALE, bool RELU, bool GATHER, bool DOT>
__global__ void __launch_bounds__(512, 1) k_linear(
    const float* __restrict__ A, const float* __restrict__ B,
    const float* __restrict__ inv,
    const float* __restrict__ W1, const float* __restrict__ W2,
    const float* __restrict__ b1, const float* __restrict__ b2,
    const int* __restrict__ lrow, const int* __restrict__ lcol,
    const float* __restrict__ wp2, const float* __restrict__ bp2,
    float* __restrict__ out, int n)
{
    extern __shared__ float sm[];
    float2* Wp   = (float2*)sm;                    // PARTS * 64 * 128 float2
    float*  Abuf = sm + PARTS * 16384;             // 2 * 32 * 128 floats
    float*  bs   = Abuf + 8192;                    // 128
    float*  w2s  = bs + 128;                       // 128
    float*  lsum = w2s + 128;                      // 32

    const int tid = threadIdx.x;

    for (int p = 0; p < PARTS; p++)
        for (int idx = tid; idx < 8192; idx += 512) {
            int k2 = idx >> 7, c = idx & 127;
            const float* src;
            if (GATHER) src = W1 + c * 256 + p * 128 + 2 * k2;
            else        src = ((p == 1) ? W2 : W1) + c * 128 + 2 * k2;
            Wp[p * 8192 + idx] = *(const float2*)src;
        }
    for (int j = tid; j < 128; j += 512) {
        bs[j] = b1[j] + (b2 ? b2[j] : 0.0f);
        if (DOT) w2s[j] = wp2[j];
    }
    __syncthreads();

    const int jt = tid & 31;
    const int w  = tid >> 5;
    const int g  = w >> 2;
    const int cq = (w & 3) * 32;

    const int ntiles  = (n + 31) >> 5;
    const int bid     = (int)blockIdx.x;
    const int myTiles = (ntiles > bid) ? ((ntiles - bid + GRID - 1) / GRID) : 0;
    const int nchunks = myTiles * PARTS;

    auto issue = [&](int cc) {
        if (cc < nchunks) {
            const int tile = bid + (cc / PARTS) * GRID;
            const int part = (PARTS == 2) ? (cc & 1) : 0;
            const int n0 = tile << 5;
            float* dst = Abuf + (cc & 1) * 4096;
            #pragma unroll
            for (int r = 0; r < 2; r++) {
                int idx  = tid + r * 512;          // 0..1023
                int node = idx >> 5, seg = idx & 31;
                int gn = n0 + node;
                float* d = dst + node * 128 + seg * 4;
                if (gn < n) {
                    const float* src;
                    if (GATHER) {
                        int row = part ? (OFF_TR + lcol[gn]) : lrow[gn];
                        src = B + (size_t)row * 128 + seg * 4;
                    } else {
                        src = ((PARTS == 2 && part) ? B : A) + (size_t)gn * 128 + seg * 4;
                    }
                    cpa16(d, src);
                } else {
                    *(float4*)d = make_float4(0.f, 0.f, 0.f, 0.f);
                }
            }
        }
        asm volatile("cp.async.commit_group;" ::: "memory");
    };

    auto compute = [&](unsigned long long (&acc)[8], const float* Ab, const float2* Wpp) {
        #pragma unroll 2
        for (int k4 = 0; k4 < 32; k4++) {
            unsigned long long w0 = *(const unsigned long long*)(Wpp + (2 * k4) * 128 + cq + jt);
            unsigned long long w1 = *(const unsigned long long*)(Wpp + (2 * k4 + 1) * 128 + cq + jt);
            ulonglong2 a[8];
            #pragma unroll
            for (int i = 0; i < 8; i++)
                a[i] = *(const ulonglong2*)(Ab + i * 128 + k4 * 4);
            #pragma unroll
            for (int i = 0; i < 8; i++) fma2(acc[i], a[i].x, w0);
            #pragma unroll
            for (int i = 0; i < 8; i++) fma2(acc[i], a[i].y, w1);
        }
    };

    unsigned long long accA[8], accB[8];
    float invr[8];

    issue(0);
    if (nchunks > 1) issue(1); else asm volatile("cp.async.commit_group;" ::: "memory");

    for (int cc = 0; cc < nchunks; cc++) {
        const int part = (PARTS == 2) ? (cc & 1) : 0;
        const int tile = bid + (cc / PARTS) * GRID;
        const int n0 = tile << 5;

        asm volatile("cp.async.wait_group 1;" ::: "memory");
        __syncthreads();

        if (SCALE && part == PARTS - 1) {
            #pragma unroll
            for (int i = 0; i < 8; i++) {
                int gn = n0 + g * 8 + i;
                invr[i] = (gn < n) ? inv[gn] : 1.0f;
            }
        }

        const float* Ab = Abuf + (cc & 1) * 4096 + g * 8 * 128;
        if (PARTS == 2 && part == 1) {
            #pragma unroll
            for (int i = 0; i < 8; i++) accB[i] = 0ull;
            compute(accB, Ab, Wp + 8192);
        } else {
            #pragma unroll
            for (int i = 0; i < 8; i++) accA[i] = 0ull;
            compute(accA, Ab, Wp);
        }
        __syncthreads();
        issue(cc + 2);

        if (part == PARTS - 1) {
            if (DOT) {
                if (tid < 32) lsum[tid] = 0.f;
                __syncthreads();
                #pragma unroll
                for (int i = 0; i < 8; i++) {
                    U64F2 ta; ta.u = accA[i];
                    float v = ta.f.x + ta.f.y;
                    if (PARTS == 2) { U64F2 tb; tb.u = accB[i]; v += tb.f.x + tb.f.y; }
                    v += bs[cq + jt];
                    v = fmaxf(v, 0.f);
                    float p = v * w2s[cq + jt];
                    #pragma unroll
                    for (int off = 16; off > 0; off >>= 1)
                        p += __shfl_xor_sync(0xffffffffu, p, off);
                    if (jt == 0) atomicAdd(&lsum[g * 8 + i], p);
                }
                __syncthreads();
                if (tid < 32) {
                    int gn = n0 + tid;
                    if (gn < n) out[gn] = lsum[tid] + bp2[0];
                }
                __syncthreads();
            } else {
                #pragma unroll
                for (int i = 0; i < 8; i++) {
                    int gn = n0 + g * 8 + i;
                    if (gn < n) {
                        U64F2 ta; ta.u = accA[i];
                        float v = ta.f.x + ta.f.y;
                        if (SCALE) v *= invr[i];
                        if (PARTS == 2) { U64F2 tb; tb.u = accB[i]; v += tb.f.x + tb.f.y; }
                        v += bs[cq + jt];
                        if (RELU) v = fmaxf(v, 0.f);
                        out[(size_t)gn * 128 + cq + jt] = v;
                    }
                }
            }
        }
    }
}

// ---------------- launch ----------------
extern "C" void kernel_launch(void* const* d_in, const int* in_sizes, int n_in,
                              void* d_out, int out_size)
{
    const int*   pl_ids   = (const int*)  d_in[0];
    const int*   ar_ids   = (const int*)  d_in[1];
    const float* track_x  = (const float*)d_in[2];
    const int*   src_pt   = (const int*)  d_in[3];
    const int*   dst_pt   = (const int*)  d_in[4];
    const int*   src_ta   = (const int*)  d_in[5];
    const int*   dst_ta   = (const int*)  d_in[6];
    const int*   lab_row  = (const int*)  d_in[7];
    const int*   lab_col  = (const int*)  d_in[8];
    const float* pl_table = (const float*)d_in[9];
    const float* ar_table = (const float*)d_in[10];
    const float* Wtr      = (const float*)d_in[11];
    const float* btr      = (const float*)d_in[12];
    const float* type_tab = (const float*)d_in[13];
    const float* Wl0      = (const float*)d_in[14];
    const float* bl0      = (const float*)d_in[15];
    const float* Wr0      = (const float*)d_in[16];
    const float* Wl1      = (const float*)d_in[17];
    const float* bl1      = (const float*)d_in[18];
    const float* Wr1      = (const float*)d_in[19];
    const float* Wp1      = (const float*)d_in[20];
    const float* bp1      = (const float*)d_in[21];
    const float* Wp2      = (const float*)d_in[22];
    const float* bp2      = (const float*)d_in[23];
    float* out = (float*)d_out;

    float *x, *y, *agg, *inv; int* deg;
    cudaGetSymbolAddress((void**)&x,   g_x);
    cudaGetSymbolAddress((void**)&y,   g_y);
    cudaGetSymbolAddress((void**)&agg, g_agg);
    cudaGetSymbolAddress((void**)&inv, g_inv);
    cudaGetSymbolAddress((void**)&deg, g_deg);

    const int SMEM_P2 = (2 * 16384 + 8192 + 288) * 4;   // 165376
    const int SMEM_P1 = (1 * 16384 + 8192 + 288) * 4;   // 99840

    cudaFuncSetAttribute(k_linear<1, false, false, false, false>, cudaFuncAttributeMaxDynamicSharedMemorySize, SMEM_P1);
    cudaFuncSetAttribute(k_linear<2, true,  true,  false, false>, cudaFuncAttributeMaxDynamicSharedMemorySize, SMEM_P2);
    cudaFuncSetAttribute(k_linear<2, false, true,  true,  true >, cudaFuncAttributeMaxDynamicSharedMemorySize, SMEM_P2);

    // launch order puts k_scatter at ncu's -s 5 slot
    k_embed<<<(NPL * 32 + 255) / 256, 256>>>(pl_ids, pl_table, type_tab, x, NPL);       // 1
    k_embed<<<(NAR * 32 + 255) / 256, 256>>>(ar_ids, ar_table, type_tab + 2 * H,        // 2
                                             x + (size_t)OFF_AR * H, NAR);
    k_linear<1, false, false, false, false><<<GRID, 512, SMEM_P1>>>(                    // 3
        track_x, nullptr, nullptr, Wtr, nullptr, btr, type_tab + H,
        nullptr, nullptr, nullptr, nullptr, x + (size_t)OFF_TR * H, NTR);

    const long long sc_threads = (long long)(EPT + ETA) * 32;
    const int sc_blocks = (int)((sc_threads + 255) / 256);

    cudaMemsetAsync(agg, 0, (size_t)NT * H * sizeof(float));                            // 4
    k_scatter<<<sc_blocks, 256>>>(x, src_pt, dst_pt, src_ta, dst_ta);                   // 5 <- profiled

    cudaMemsetAsync(deg, 0, (size_t)NT * sizeof(int));                                  // 6
    k_deg<<<(EPT + ETA + 255) / 256, 256>>>(src_pt, dst_pt, src_ta, dst_ta);            // 7
    k_inv<<<(NT + 255) / 256, 256>>>();                                                 // 8

    k_linear<2, true, true, false, false><<<GRID, 512, SMEM_P2>>>(                      // 9
        agg, x, inv, Wl0, Wr0, bl0, nullptr,
        nullptr, nullptr, nullptr, nullptr, y, NT);

    cudaMemsetAsync(agg, 0, (size_t)NT * H * sizeof(float));                            // 10
    k_scatter<<<sc_blocks, 256>>>(y, src_pt, dst_pt, src_ta, dst_ta);                   // 11
    k_linear<2, true, true, false, false><<<GRID, 512, SMEM_P2>>>(                      // 12
        agg, y, inv, Wl1, Wr1, bl1, nullptr,
        nullptr, nullptr, nullptr, nullptr, x, NT);

    k_linear<2, false, true, true, true><<<GRID, 512, SMEM_P2>>>(                       // 13
        nullptr, x, nullptr, Wp1, nullptr, bp1, nullptr,
        lab_row, lab_col, Wp2, bp2, out, LBL);
}

// round 5
// speedup vs baseline: 1.0006x; 1.0006x over previous
#include <cuda_runtime.h>
#include <cstddef>

#define H       128
#define NPL     100000
#define NTR     200000
#define NAR     50000
#define NT      350000
#define OFF_TR  100000
#define OFF_AR  300000
#define EPT     500000
#define ETA     200000
#define LBL     100000
#define GRID    152

// ---------------- scratch ----------------
__device__ float g_x  [(size_t)NT * H];
__device__ float g_y  [(size_t)NT * H];
__device__ float g_agg[(size_t)NT * H];
__device__ float g_inv[NT];
__device__ int   g_deg[NT];

// ---------------- helpers ----------------
__device__ __forceinline__ void fma2(unsigned long long& d,
                                     unsigned long long a, unsigned long long b) {
    asm("fma.rn.f32x2 %0, %1, %2, %0;" : "+l"(d) : "l"(a), "l"(b));
}

union U64F2 { unsigned long long u; float2 f; };

__device__ __forceinline__ void red4(float* p, float4 v) {
    asm volatile("red.global.add.v4.f32 [%0], {%1,%2,%3,%4};"
                 :: "l"(p), "f"(v.x), "f"(v.y), "f"(v.z), "f"(v.w) : "memory");
}

__device__ __forceinline__ void cpa16(float* smem_dst, const float* gsrc) {
    unsigned ds = (unsigned)__cvta_generic_to_shared(smem_dst);
    asm volatile("cp.async.cg.shared.global [%0], [%1], 16;" :: "r"(ds), "l"(gsrc) : "memory");
}

// ---------------- embedding gather (pl / ar) ----------------
__global__ void k_embed(const int* __restrict__ ids, const float* __restrict__ table,
                        const float* __restrict__ trow, float* __restrict__ out, int n)
{
    int t = blockIdx.x * blockDim.x + threadIdx.x;
    if (t >= n * 32) return;
    int i = t >> 5, c = t & 31;
    float4 v  = ((const float4*)(table + (size_t)ids[i] * H))[c];
    float4 tv = ((const float4*)trow)[c];
    v.x += tv.x; v.y += tv.y; v.z += tv.z; v.w += tv.w;
    ((float4*)(out + (size_t)i * H))[c] = v;
}

// ---------------- degree count ----------------
__global__ void k_deg(const int* __restrict__ sp, const int* __restrict__ dp,
                      const int* __restrict__ st, const int* __restrict__ dt)
{
    int e = blockIdx.x * blockDim.x + threadIdx.x;
    if (e < EPT) {
        int s = sp[e], d = dp[e] + OFF_TR;
        atomicAdd(&g_deg[d], 1);
        atomicAdd(&g_deg[s], 1);
    } else if (e < EPT + ETA) {
        int i = e - EPT;
        int s = st[i] + OFF_TR, d = dt[i] + OFF_AR;
        atomicAdd(&g_deg[d], 1);
        atomicAdd(&g_deg[s], 1);
    }
}

__global__ void k_inv()
{
    int i = blockIdx.x * blockDim.x + threadIdx.x;
    if (i < NT) g_inv[i] = 1.0f / fmaxf((float)g_deg[i], 1.0f);
}

// ---------------- edge scatter ----------------
__global__ void k_scatter(const float* __restrict__ x,
                          const int* __restrict__ sp, const int* __restrict__ dp,
                          const int* __restrict__ st, const int* __restrict__ dt)
{
    long long t = (long long)blockIdx.x * blockDim.x + threadIdx.x;
    if (t >= (long long)(EPT + ETA) * 32) return;
    int e = (int)(t >> 5), c = (int)(t & 31);
    int a, b;
    if (e < EPT) { a = sp[e];          b = dp[e] + OFF_TR; }
    else { int i = e - EPT; a = st[i] + OFF_TR; b = dt[i] + OFF_AR; }
    float4 va = ((const float4*)(x + (size_t)a * H))[c];
    float4 vb = ((const float4*)(x + (size_t)b * H))[c];
    red4(g_agg + (size_t)b * H + 4 * c, va);
    red4(g_agg + (size_t)a * H + 4 * c, vb);
}

// ---------------- pipelined f32x2 linear ----------------
// 512 thr / 16 warps; tile = 32 nodes; chunk = (tile, part), K=128 per part.
// warp w: node group g=w>>2 (8 nodes), col quarter cq=(w&3)*32; lane owns 1 col.
// A-chunks double-buffered via cp.async (16KB each), prefetch distance 1.
// PARTS=2: partA -> accA (scaled by inv at epilogue), partB -> accB.
// GATHER: A rows from B-base via lrow/lcol. DOT: wp2-dot epilogue (logits).
template<int PARTS, bool SCALE, bool RELU, bool GATHER, bool DOT>
__global__ void __launch_bounds__(512, 1) k_linear(
    const float* __restrict__ A, const float* __restrict__ B,
    const float* __restrict__ inv,
    const float* __restrict__ W1, const float* __restrict__ W2,
    const float* __restrict__ b1, const float* __restrict__ b2,
    const int* __restrict__ lrow, const int* __restrict__ lcol,
    const float* __restrict__ wp2, const float* __restrict__ bp2,
    float* __restrict__ out, int n)
{
    extern __shared__ float sm[];
    float2* Wp   = (float2*)sm;                    // PARTS * 64 * 128 float2
    float*  Abuf = sm + PARTS * 16384;             // 2 * 32 * 128 floats
    float*  bs   = Abuf + 8192;                    // 128
    float*  w2s  = bs + 128;                       // 128
    float*  lsum = w2s + 128;                      // 32

    const int tid = threadIdx.x;

    for (int p = 0; p < PARTS; p++)
        for (int idx = tid; idx < 8192; idx += 512) {
            int k2 = idx >> 7, c = idx & 127;
            const float* src;
            if (GATHER) src = W1 + c * 256 + p * 128 + 2 * k2;
            else        src = ((p == 1) ? W2 : W1) + c * 128 + 2 * k2;
            Wp[p * 8192 + idx] = *(const float2*)src;
        }
    for (int j = tid; j < 128; j += 512) {
        bs[j] = b1[j] + (b2 ? b2[j] : 0.0f);
        if (DOT) w2s[j] = wp2[j];
    }
    __syncthreads();

    const int jt = tid & 31;
    const int w  = tid >> 5;
    const int g  = w >> 2;
    const int cq = (w & 3) * 32;

    const int ntiles  = (n + 31) >> 5;
    const int bid     = (int)blockIdx.x;
    const int myTiles = (ntiles > bid) ? ((ntiles - bid + GRID - 1) / GRID) : 0;
    const int nchunks = myTiles * PARTS;

    auto issue = [&](int cc) {
        if (cc < nchunks) {
            const int tile = bid + (cc / PARTS) * GRID;
            const int part = (PARTS == 2) ? (cc & 1) : 0;
            const int n0 = tile << 5;
            float* dst = Abuf + (cc & 1) * 4096;
            #pragma unroll
            for (int r = 0; r < 2; r++) {
                int idx  = tid + r * 512;          // 0..1023
                int node = idx >> 5, seg = idx & 31;
                int gn = n0 + node;
                float* d = dst + node * 128 + seg * 4;
                if (gn < n) {
                    const float* src;
                    if (GATHER) {
                        int row = part ? (OFF_TR + lcol[gn]) : lrow[gn];
                        src = B + (size_t)row * 128 + seg * 4;
                    } else {
                        src = ((PARTS == 2 && part) ? B : A) + (size_t)gn * 128 + seg * 4;
                    }
                    cpa16(d, src);
                } else {
                    *(float4*)d = make_float4(0.f, 0.f, 0.f, 0.f);
                }
            }
        }
        asm volatile("cp.async.commit_group;" ::: "memory");
    };

    auto compute = [&](unsigned long long (&acc)[8], const float* Ab, const float2* Wpp) {
        #pragma unroll 2
        for (int k4 = 0; k4 < 32; k4++) {
            unsigned long long w0 = *(const unsigned long long*)(Wpp + (2 * k4) * 128 + cq + jt);
            unsigned long long w1 = *(const unsigned long long*)(Wpp + (2 * k4 + 1) * 128 + cq + jt);
            ulonglong2 a[8];
            #pragma unroll
            for (int i = 0; i < 8; i++)
                a[i] = *(const ulonglong2*)(Ab + i * 128 + k4 * 4);
            #pragma unroll
            for (int i = 0; i < 8; i++) fma2(acc[i], a[i].x, w0);
            #pragma unroll
            for (int i = 0; i < 8; i++) fma2(acc[i], a[i].y, w1);
        }
    };

    unsigned long long accA[8], accB[8];
    float invr[8];

    issue(0);
    if (nchunks > 1) issue(1); else asm volatile("cp.async.commit_group;" ::: "memory");

    for (int cc = 0; cc < nchunks; cc++) {
        const int part = (PARTS == 2) ? (cc & 1) : 0;
        const int tile = bid + (cc / PARTS) * GRID;
        const int n0 = tile << 5;

        asm volatile("cp.async.wait_group 1;" ::: "memory");
        __syncthreads();

        if (SCALE && part == PARTS - 1) {
            #pragma unroll
            for (int i = 0; i < 8; i++) {
                int gn = n0 + g * 8 + i;
                invr[i] = (gn < n) ? inv[gn] : 1.0f;
            }
        }

        const float* Ab = Abuf + (cc & 1) * 4096 + g * 8 * 128;
        if (PARTS == 2 && part == 1) {
            #pragma unroll
            for (int i = 0; i < 8; i++) accB[i] = 0ull;
            compute(accB, Ab, Wp + 8192);
        } else {
            #pragma unroll
            for (int i = 0; i < 8; i++) accA[i] = 0ull;
            compute(accA, Ab, Wp);
        }
        __syncthreads();
        issue(cc + 2);

        if (part == PARTS - 1) {
            if (DOT) {
                if (tid < 32) lsum[tid] = 0.f;
                __syncthreads();
                #pragma unroll
                for (int i = 0; i < 8; i++) {
                    U64F2 ta; ta.u = accA[i];
                    float v = ta.f.x + ta.f.y;
                    if (PARTS == 2) { U64F2 tb; tb.u = accB[i]; v += tb.f.x + tb.f.y; }
                    v += bs[cq + jt];
                    v = fmaxf(v, 0.f);
                    float p = v * w2s[cq + jt];
                    #pragma unroll
                    for (int off = 16; off > 0; off >>= 1)
                        p += __shfl_xor_sync(0xffffffffu, p, off);
                    if (jt == 0) atomicAdd(&lsum[g * 8 + i], p);
                }
                __syncthreads();
                if (tid < 32) {
                    int gn = n0 + tid;
                    if (gn < n) out[gn] = lsum[tid] + bp2[0];
                }
                __syncthreads();
            } else {
                #pragma unroll
                for (int i = 0; i < 8; i++) {
                    int gn = n0 + g * 8 + i;
                    if (gn < n) {
                        U64F2 ta; ta.u = accA[i];
                        float v = ta.f.x + ta.f.y;
                        if (SCALE) v *= invr[i];
                        if (PARTS == 2) { U64F2 tb; tb.u = accB[i]; v += tb.f.x + tb.f.y; }
                        v += bs[cq + jt];
                        if (RELU) v = fmaxf(v, 0.f);
                        out[(size_t)gn * 128 + cq + jt] = v;
                    }
                }
            }
        }
    }
}

// ---------------- launch ----------------
extern "C" void kernel_launch(void* const* d_in, const int* in_sizes, int n_in,
                              void* d_out, int out_size)
{
    const int*   pl_ids   = (const int*)  d_in[0];
    const int*   ar_ids   = (const int*)  d_in[1];
    const float* track_x  = (const float*)d_in[2];
    const int*   src_pt   = (const int*)  d_in[3];
    const int*   dst_pt   = (const int*)  d_in[4];
    const int*   src_ta   = (const int*)  d_in[5];
    const int*   dst_ta   = (const int*)  d_in[6];
    const int*   lab_row  = (const int*)  d_in[7];
    const int*   lab_col  = (const int*)  d_in[8];
    const float* pl_table = (const float*)d_in[9];
    const float* ar_table = (const float*)d_in[10];
    const float* Wtr      = (const float*)d_in[11];
    const float* btr      = (const float*)d_in[12];
    const float* type_tab = (const float*)d_in[13];
    const float* Wl0      = (const float*)d_in[14];
    const float* bl0      = (const float*)d_in[15];
    const float* Wr0      = (const float*)d_in[16];
    const float* Wl1      = (const float*)d_in[17];
    const float* bl1      = (const float*)d_in[18];
    const float* Wr1      = (const float*)d_in[19];
    const float* Wp1      = (const float*)d_in[20];
    const float* bp1      = (const float*)d_in[21];
    const float* Wp2      = (const float*)d_in[22];
    const float* bp2      = (const float*)d_in[23];
    float* out = (float*)d_out;

    float *x, *y, *agg, *inv; int* deg;
    cudaGetSymbolAddress((void**)&x,   g_x);
    cudaGetSymbolAddress((void**)&y,   g_y);
    cudaGetSymbolAddress((void**)&agg, g_agg);
    cudaGetSymbolAddress((void**)&inv, g_inv);
    cudaGetSymbolAddress((void**)&deg, g_deg);

    const int SMEM_P2 = (2 * 16384 + 8192 + 288) * 4;   // 165376
    const int SMEM_P1 = (1 * 16384 + 8192 + 288) * 4;   // 99840

    cudaFuncSetAttribute(k_linear<1, false, false, false, false>, cudaFuncAttributeMaxDynamicSharedMemorySize, SMEM_P1);
    cudaFuncSetAttribute(k_linear<2, true,  true,  false, false>, cudaFuncAttributeMaxDynamicSharedMemorySize, SMEM_P2);
    cudaFuncSetAttribute(k_linear<2, false, true,  true,  true >, cudaFuncAttributeMaxDynamicSharedMemorySize, SMEM_P2);

    // launch order puts k_scatter at ncu's -s 5 slot
    k_embed<<<(NPL * 32 + 255) / 256, 256>>>(pl_ids, pl_table, type_tab, x, NPL);       // 1
    k_embed<<<(NAR * 32 + 255) / 256, 256>>>(ar_ids, ar_table, type_tab + 2 * H,        // 2
                                             x + (size_t)OFF_AR * H, NAR);
    k_linear<1, false, false, false, false><<<GRID, 512, SMEM_P1>>>(                    // 3
        track_x, nullptr, nullptr, Wtr, nullptr, btr, type_tab + H,
        nullptr, nullptr, nullptr, nullptr, x + (size_t)OFF_TR * H, NTR);

    const long long sc_threads = (long long)(EPT + ETA) * 32;
    const int sc_blocks = (int)((sc_threads + 255) / 256);

    cudaMemsetAsync(agg, 0, (size_t)NT * H * sizeof(float));                            // 4
    k_scatter<<<sc_blocks, 256>>>(x, src_pt, dst_pt, src_ta, dst_ta);                   // 5 <- profiled

    cudaMemsetAsync(deg, 0, (size_t)NT * sizeof(int));                                  // 6
    k_deg<<<(EPT + ETA + 255) / 256, 256>>>(src_pt, dst_pt, src_ta, dst_ta);            // 7
    k_inv<<<(NT + 255) / 256, 256>>>();                                                 // 8

    k_linear<2, true, true, false, false><<<GRID, 512, SMEM_P2>>>(                      // 9
        agg, x, inv, Wl0, Wr0, bl0, nullptr,
        nullptr, nullptr, nullptr, nullptr, y, NT);

    cudaMemsetAsync(agg, 0, (size_t)NT * H * sizeof(float));                            // 10
    k_scatter<<<sc_blocks, 256>>>(y, src_pt, dst_pt, src_ta, dst_ta);                   // 11
    k_linear<2, true, true, false, false><<<GRID, 512, SMEM_P2>>>(                      // 12
        agg, y, inv, Wl1, Wr1, bl1, nullptr,
        nullptr, nullptr, nullptr, nullptr, x, NT);

    k_linear<2, false, true, true, true><<<GRID, 512, SMEM_P2>>>(                       // 13
        nullptr, x, nullptr, Wp1, nullptr, bp1, nullptr,
        lab_row, lab_col, Wp2, bp2, out, LBL);
}

// round 6
// speedup vs baseline: 1.2024x; 1.2016x over previous
#include <cuda_runtime.h>
#include <cstddef>

#define H       128
#define NPL     100000
#define NTR     200000
#define NAR     50000
#define NT      350000
#define OFF_TR  100000
#define OFF_AR  300000
#define EPT     500000
#define ETA     200000
#define LBL     100000
#define GRID    152

// ---------------- scratch ----------------
__device__ float g_x  [(size_t)NT * H];
__device__ float g_y  [(size_t)NT * H];
__device__ float g_agg[(size_t)NT * H];
__device__ float g_inv[NT];
__device__ int   g_deg[NT];

// ---------------- helpers ----------------
typedef unsigned long long u64;

__device__ __forceinline__ void fma2(u64& d, u64 a, u64 b) {
    asm("fma.rn.f32x2 %0, %1, %2, %0;" : "+l"(d) : "l"(a), "l"(b));
}
__device__ __forceinline__ u64 dup(float a) {
    u64 r; asm("mov.b64 %0, {%1, %1};" : "=l"(r) : "f"(a)); return r;
}
union U64F2 { u64 u; float2 f; };

__device__ __forceinline__ void red4(float* p, float4 v) {
    asm volatile("red.global.add.v4.f32 [%0], {%1,%2,%3,%4};"
                 :: "l"(p), "f"(v.x), "f"(v.y), "f"(v.z), "f"(v.w) : "memory");
}

// ---------------- combined embedding gather (pl + ar) ----------------
__global__ void k_embed2(const int* __restrict__ pl, const int* __restrict__ ar,
                         const float* __restrict__ plt, const float* __restrict__ art,
                         const float* __restrict__ tt, float* __restrict__ x)
{
    int t = blockIdx.x * blockDim.x + threadIdx.x;
    if (t < NPL * 32) {
        int i = t >> 5, c = t & 31;
        float4 v  = ((const float4*)(plt + (size_t)pl[i] * H))[c];
        float4 tv = ((const float4*)tt)[c];
        v.x += tv.x; v.y += tv.y; v.z += tv.z; v.w += tv.w;
        ((float4*)(x + (size_t)i * H))[c] = v;
    } else {
        t -= NPL * 32;
        if (t >= NAR * 32) return;
        int i = t >> 5, c = t & 31;
        float4 v  = ((const float4*)(art + (size_t)ar[i] * H))[c];
        float4 tv = ((const float4*)(tt + 2 * H))[c];
        v.x += tv.x; v.y += tv.y; v.z += tv.z; v.w += tv.w;
        ((float4*)(x + (size_t)(OFF_AR + i) * H))[c] = v;
    }
}

// ---------------- degree count ----------------
__global__ void k_deg(const int* __restrict__ sp, const int* __restrict__ dp,
                      const int* __restrict__ st, const int* __restrict__ dt)
{
    int e = blockIdx.x * blockDim.x + threadIdx.x;
    if (e < EPT) {
        atomicAdd(&g_deg[dp[e] + OFF_TR], 1);
        atomicAdd(&g_deg[sp[e]], 1);
    } else if (e < EPT + ETA) {
        int i = e - EPT;
        atomicAdd(&g_deg[dt[i] + OFF_AR], 1);
        atomicAdd(&g_deg[st[i] + OFF_TR], 1);
    }
}

__global__ void k_inv()
{
    int i = blockIdx.x * blockDim.x + threadIdx.x;
    if (i < NT) g_inv[i] = 1.0f / fmaxf((float)g_deg[i], 1.0f);
}

// ---------------- edge scatter (77% DRAM roofline -- leave alone) ----------------
__global__ void k_scatter(const float* __restrict__ x,
                          const int* __restrict__ sp, const int* __restrict__ dp,
                          const int* __restrict__ st, const int* __restrict__ dt)
{
    long long t = (long long)blockIdx.x * blockDim.x + threadIdx.x;
    if (t >= (long long)(EPT + ETA) * 32) return;
    int e = (int)(t >> 5), c = (int)(t & 31);
    int a, b;
    if (e < EPT) { a = sp[e];          b = dp[e] + OFF_TR; }
    else { int i = e - EPT; a = st[i] + OFF_TR; b = dt[i] + OFF_AR; }
    float4 va = ((const float4*)(x + (size_t)a * H))[c];
    float4 vb = ((const float4*)(x + (size_t)b * H))[c];
    red4(g_agg + (size_t)b * H + 4 * c, va);
    red4(g_agg + (size_t)a * H + 4 * c, vb);
}

// ---------------- 2D-register-tiled f32x2 GEMM ----------------
// 512 thr / 16 warps (4x4 grid). Block tile 128 nodes x 128 cols, K=KK.
// Warp tile 32x32; lane tile 4 nodes x 8 cols (col-paired f32x2 accumulators).
// WT[k][132] resident (transposed W, [W1;W2] concat when DUAL).
// Ash[k][132] transposed A chunk (32 k's), restaged per chunk.
// Per k per lane: 1 A LDS.128 + 2 W LDS.128 + 4 dup + 16 FFMA2 -> FMA2-bound.
// SCALE: inv[node] folded into A(agg)-part staging.
// GATHER: A rows via lrow/lcol (predictor concat). DOT: Wp2-dot epilogue.
template<int KK, bool DUAL, bool SCALE, bool RELU, bool GATHER, bool DOT>
__global__ void __launch_bounds__(512, 1) k_gemm(
    const float* __restrict__ A, const float* __restrict__ B,
    const float* __restrict__ inv,
    const float* __restrict__ W1, const float* __restrict__ W2,
    const float* __restrict__ b1, const float* __restrict__ b2,
    const int* __restrict__ lrow, const int* __restrict__ lcol,
    const float* __restrict__ wp2, const float* __restrict__ bp2,
    float* __restrict__ out, int n)
{
    extern __shared__ float sm[];
    float* WT   = sm;                     // KK x 132
    float* Ash  = WT + KK * 132;          // 32 x 132
    float* bs   = Ash + 32 * 132;         // 128
    float* w2s  = bs + 128;               // 128
    float* lsum = w2s + 128;              // 128

    const int tid = threadIdx.x;

    // ---- stage WT (transposed weights, once per block) ----
    for (int idx = tid; idx < KK * 32; idx += 512) {
        int c = idx / (KK / 4), kq = idx % (KK / 4);
        const float* src;
        if (DUAL) src = (kq < 32) ? (W1 + c * 128 + kq * 4)
                                  : (W2 + c * 128 + (kq - 32) * 4);
        else      src = W1 + c * KK + kq * 4;
        float4 v = *(const float4*)src;
        WT[(kq * 4 + 0) * 132 + c] = v.x;
        WT[(kq * 4 + 1) * 132 + c] = v.y;
        WT[(kq * 4 + 2) * 132 + c] = v.z;
        WT[(kq * 4 + 3) * 132 + c] = v.w;
    }
    for (int j = tid; j < 128; j += 512) {
        bs[j] = b1[j] + (b2 ? b2[j] : 0.0f);
        if (DOT) w2s[j] = wp2[j];
    }
    __syncthreads();

    const int w  = tid >> 5, jt = tid & 31;
    const int wr = w >> 2,   wc = w & 3;
    const int lr = jt >> 2,  lc = jt & 3;
    const int nodeoff = wr * 32 + lr * 4;
    const int coloff  = wc * 32 + lc * 8;

    const int ntiles = (n + 127) >> 7;
    const int snode = tid & 127, skg = tid >> 7;   // staging: node, k-group(0..3)

    for (int tile = blockIdx.x; tile < ntiles; tile += GRID) {
        const int n0 = tile << 7;

        u64 acc[4][4];
        #pragma unroll
        for (int i = 0; i < 4; i++)
            #pragma unroll
            for (int p = 0; p < 4; p++) acc[i][p] = 0ull;

        if (DOT && tid < 128) lsum[tid] = 0.f;

        #pragma unroll 1
        for (int kc = 0; kc < KK / 32; kc++) {
            __syncthreads();   // protect previous chunk's Ash reads
            {
                int gn = n0 + snode;
                float4 v0 = make_float4(0.f,0.f,0.f,0.f), v1 = v0;
                if (gn < n) {
                    const float* src;
                    if (GATHER) {
                        int row = (kc < 4) ? lrow[gn] : (OFF_TR + lcol[gn]);
                        src = B + (size_t)row * 128 + (kc & 3) * 32 + skg * 8;
                    } else if (DUAL) {
                        src = (kc < 4) ? (A + (size_t)gn * 128 + kc * 32 + skg * 8)
                                       : (B + (size_t)gn * 128 + (kc - 4) * 32 + skg * 8);
                    } else {
                        src = A + (size_t)gn * KK + kc * 32 + skg * 8;
                    }
                    v0 = ((const float4*)src)[0];
                    v1 = ((const float4*)src)[1];
                    if (SCALE && kc < 4) {
                        float s = inv[gn];
                        v0.x *= s; v0.y *= s; v0.z *= s; v0.w *= s;
                        v1.x *= s; v1.y *= s; v1.z *= s; v1.w *= s;
                    }
                }
                float* ab = Ash + (skg * 8) * 132 + snode;
                ab[0 * 132] = v0.x; ab[1 * 132] = v0.y;
                ab[2 * 132] = v0.z; ab[3 * 132] = v0.w;
                ab[4 * 132] = v1.x; ab[5 * 132] = v1.y;
                ab[6 * 132] = v1.z; ab[7 * 132] = v1.w;
            }
            __syncthreads();

            const float* wbase = WT + (size_t)(kc * 32) * 132 + coloff;
            #pragma unroll 4
            for (int kk = 0; kk < 32; kk++) {
                float4 a = *(const float4*)(Ash + kk * 132 + nodeoff);
                const float* wrp = wbase + kk * 132;
                ulonglong2 w01 = *(const ulonglong2*)wrp;
                ulonglong2 w23 = *(const ulonglong2*)(wrp + 4);
                u64 d0 = dup(a.x), d1 = dup(a.y), d2 = dup(a.z), d3 = dup(a.w);
                fma2(acc[0][0], d0, w01.x); fma2(acc[0][1], d0, w01.y);
                fma2(acc[0][2], d0, w23.x); fma2(acc[0][3], d0, w23.y);
                fma2(acc[1][0], d1, w01.x); fma2(acc[1][1], d1, w01.y);
                fma2(acc[1][2], d1, w23.x); fma2(acc[1][3], d1, w23.y);
                fma2(acc[2][0], d2, w01.x); fma2(acc[2][1], d2, w01.y);
                fma2(acc[2][2], d2, w23.x); fma2(acc[2][3], d2, w23.y);
                fma2(acc[3][0], d3, w01.x); fma2(acc[3][1], d3, w01.y);
                fma2(acc[3][2], d3, w23.x); fma2(acc[3][3], d3, w23.y);
            }
        }

        // ---- epilogue ----
        #pragma unroll
        for (int i = 0; i < 4; i++) {
            int gn = n0 + nodeoff + i;
            U64F2 p0, p1, p2, p3;
            p0.u = acc[i][0]; p1.u = acc[i][1]; p2.u = acc[i][2]; p3.u = acc[i][3];
            float v[8];
            v[0] = p0.f.x + bs[coloff + 0]; v[1] = p0.f.y + bs[coloff + 1];
            v[2] = p1.f.x + bs[coloff + 2]; v[3] = p1.f.y + bs[coloff + 3];
            v[4] = p2.f.x + bs[coloff + 4]; v[5] = p2.f.y + bs[coloff + 5];
            v[6] = p3.f.x + bs[coloff + 6]; v[7] = p3.f.y + bs[coloff + 7];
            if (RELU) {
                #pragma unroll
                for (int j = 0; j < 8; j++) v[j] = fmaxf(v[j], 0.f);
            }
            if (DOT) {
                float part = 0.f;
                #pragma unroll
                for (int j = 0; j < 8; j++) part += v[j] * w2s[coloff + j];
                part += __shfl_xor_sync(0xffffffffu, part, 1);
                part += __shfl_xor_sync(0xffffffffu, part, 2);
                if (lc == 0 && gn < n) atomicAdd(&lsum[nodeoff + i], part);
            } else if (gn < n) {
                *(float4*)(out + (size_t)gn * 128 + coloff)     = make_float4(v[0], v[1], v[2], v[3]);
                *(float4*)(out + (size_t)gn * 128 + coloff + 4) = make_float4(v[4], v[5], v[6], v[7]);
            }
        }
        if (DOT) {
            __syncthreads();
            if (tid < 128) {
                int gn = n0 + tid;
                if (gn < n) out[gn] = lsum[tid] + bp2[0];
            }
        }
    }
}

// ---------------- launch ----------------
extern "C" void kernel_launch(void* const* d_in, const int* in_sizes, int n_in,
                              void* d_out, int out_size)
{
    const int*   pl_ids   = (const int*)  d_in[0];
    const int*   ar_ids   = (const int*)  d_in[1];
    const float* track_x  = (const float*)d_in[2];
    const int*   src_pt   = (const int*)  d_in[3];
    const int*   dst_pt   = (const int*)  d_in[4];
    const int*   src_ta   = (const int*)  d_in[5];
    const int*   dst_ta   = (const int*)  d_in[6];
    const int*   lab_row  = (const int*)  d_in[7];
    const int*   lab_col  = (const int*)  d_in[8];
    const float* pl_table = (const float*)d_in[9];
    const float* ar_table = (const float*)d_in[10];
    const float* Wtr      = (const float*)d_in[11];
    const float* btr      = (const float*)d_in[12];
    const float* type_tab = (const float*)d_in[13];
    const float* Wl0      = (const float*)d_in[14];
    const float* bl0      = (const float*)d_in[15];
    const float* Wr0      = (const float*)d_in[16];
    const float* Wl1      = (const float*)d_in[17];
    const float* bl1      = (const float*)d_in[18];
    const float* Wr1      = (const float*)d_in[19];
    const float* Wp1      = (const float*)d_in[20];
    const float* bp1      = (const float*)d_in[21];
    const float* Wp2      = (const float*)d_in[22];
    const float* bp2      = (const float*)d_in[23];
    float* out = (float*)d_out;

    float *x, *y, *agg, *inv; int* deg;
    cudaGetSymbolAddress((void**)&x,   g_x);
    cudaGetSymbolAddress((void**)&y,   g_y);
    cudaGetSymbolAddress((void**)&agg, g_agg);
    cudaGetSymbolAddress((void**)&inv, g_inv);
    cudaGetSymbolAddress((void**)&deg, g_deg);

    const int SMEM_256 = (256 * 132 + 32 * 132 + 384) * 4;   // 153600
    const int SMEM_128 = (128 * 132 + 32 * 132 + 384) * 4;   // 86016

    cudaFuncSetAttribute(k_gemm<128, false, false, false, false, false>, cudaFuncAttributeMaxDynamicSharedMemorySize, SMEM_128);
    cudaFuncSetAttribute(k_gemm<256, true,  true,  true,  false, false>, cudaFuncAttributeMaxDynamicSharedMemorySize, SMEM_256);
    cudaFuncSetAttribute(k_gemm<256, false, false, true,  true,  true >, cudaFuncAttributeMaxDynamicSharedMemorySize, SMEM_256);

    // graph-node order: encode GEMM at node 5 for ncu (-s 5 profiles 5th node)
    cudaMemsetAsync(deg, 0, (size_t)NT * sizeof(int));                                  // 1
    k_deg<<<(EPT + ETA + 255) / 256, 256>>>(src_pt, dst_pt, src_ta, dst_ta);            // 2
    k_inv<<<(NT + 255) / 256, 256>>>();                                                 // 3
    k_embed2<<<((NPL + NAR) * 32 + 255) / 256, 256>>>(pl_ids, ar_ids, pl_table,         // 4
                                                      ar_table, type_tab, x);
    k_gemm<128, false, false, false, false, false><<<GRID, 512, SMEM_128>>>(            // 5 <- profiled
        track_x, nullptr, nullptr, Wtr, nullptr, btr, type_tab + H,
        nullptr, nullptr, nullptr, nullptr, x + (size_t)OFF_TR * H, NTR);

    const long long sc_threads = (long long)(EPT + ETA) * 32;
    const int sc_blocks = (int)((sc_threads + 255) / 256);

    cudaMemsetAsync(agg, 0, (size_t)NT * H * sizeof(float));                            // 6
    k_scatter<<<sc_blocks, 256>>>(x, src_pt, dst_pt, src_ta, dst_ta);                   // 7
    k_gemm<256, true, true, true, false, false><<<GRID, 512, SMEM_256>>>(               // 8
        agg, x, inv, Wl0, Wr0, bl0, nullptr,
        nullptr, nullptr, nullptr, nullptr, y, NT);

    cudaMemsetAsync(agg, 0, (size_t)NT * H * sizeof(float));                            // 9
    k_scatter<<<sc_blocks, 256>>>(y, src_pt, dst_pt, src_ta, dst_ta);                   // 10
    k_gemm<256, true, true, true, false, false><<<GRID, 512, SMEM_256>>>(               // 11
        agg, y, inv, Wl1, Wr1, bl1, nullptr,
        nullptr, nullptr, nullptr, nullptr, x, NT);

    k_gemm<256, false, false, true, true, true><<<GRID, 512, SMEM_256>>>(               // 12
        nullptr, x, nullptr, Wp1, nullptr, bp1, nullptr,
        lab_row, lab_col, Wp2, bp2, out, LBL);
}

// round 7
// speedup vs baseline: 1.2397x; 1.0311x over previous
#include <cuda_runtime.h>
#include <cstddef>

#define H       128
#define NPL     100000
#define NTR     200000
#define NAR     50000
#define NT      350000
#define OFF_TR  100000
#define OFF_AR  300000
#define EPT     500000
#define ETA     200000
#define LBL     100000
#define GRID    152

// ---------------- scratch ----------------
__device__ float g_x  [(size_t)NT * H];
__device__ float g_y  [(size_t)NT * H];
__device__ float g_agg[(size_t)NT * H];
__device__ float g_inv[NT];
__device__ int   g_deg[NT];

// ---------------- helpers ----------------
typedef unsigned long long u64;

__device__ __forceinline__ void fma2(u64& d, u64 a, u64 b) {
    asm("fma.rn.f32x2 %0, %1, %2, %0;" : "+l"(d) : "l"(a), "l"(b));
}
__device__ __forceinline__ u64 dup(float a) {
    u64 r; asm("mov.b64 %0, {%1, %1};" : "=l"(r) : "f"(a)); return r;
}
union U64F2 { u64 u; float2 f; };

__device__ __forceinline__ void red4(float* p, float4 v) {
    asm volatile("red.global.add.v4.f32 [%0], {%1,%2,%3,%4};"
                 :: "l"(p), "f"(v.x), "f"(v.y), "f"(v.z), "f"(v.w) : "memory");
}

// ---------------- combined embedding gather (pl + ar) ----------------
__global__ void k_embed2(const int* __restrict__ pl, const int* __restrict__ ar,
                         const float* __restrict__ plt, const float* __restrict__ art,
                         const float* __restrict__ tt, float* __restrict__ x)
{
    int t = blockIdx.x * blockDim.x + threadIdx.x;
    if (t < NPL * 32) {
        int i = t >> 5, c = t & 31;
        float4 v  = ((const float4*)(plt + (size_t)pl[i] * H))[c];
        float4 tv = ((const float4*)tt)[c];
        v.x += tv.x; v.y += tv.y; v.z += tv.z; v.w += tv.w;
        ((float4*)(x + (size_t)i * H))[c] = v;
    } else {
        t -= NPL * 32;
        if (t >= NAR * 32) return;
        int i = t >> 5, c = t & 31;
        float4 v  = ((const float4*)(art + (size_t)ar[i] * H))[c];
        float4 tv = ((const float4*)(tt + 2 * H))[c];
        v.x += tv.x; v.y += tv.y; v.z += tv.z; v.w += tv.w;
        ((float4*)(x + (size_t)(OFF_AR + i) * H))[c] = v;
    }
}

// ---------------- degree count ----------------
__global__ void k_deg(const int* __restrict__ sp, const int* __restrict__ dp,
                      const int* __restrict__ st, const int* __restrict__ dt)
{
    int e = blockIdx.x * blockDim.x + threadIdx.x;
    if (e < EPT) {
        atomicAdd(&g_deg[dp[e] + OFF_TR], 1);
        atomicAdd(&g_deg[sp[e]], 1);
    } else if (e < EPT + ETA) {
        int i = e - EPT;
        atomicAdd(&g_deg[dt[i] + OFF_AR], 1);
        atomicAdd(&g_deg[st[i] + OFF_TR], 1);
    }
}

__global__ void k_inv()
{
    int i = blockIdx.x * blockDim.x + threadIdx.x;
    if (i < NT) g_inv[i] = 1.0f / fmaxf((float)g_deg[i], 1.0f);
}

// ---------------- edge scatter (77% DRAM roofline -- leave alone) ----------------
__global__ void k_scatter(const float* __restrict__ x,
                          const int* __restrict__ sp, const int* __restrict__ dp,
                          const int* __restrict__ st, const int* __restrict__ dt)
{
    long long t = (long long)blockIdx.x * blockDim.x + threadIdx.x;
    if (t >= (long long)(EPT + ETA) * 32) return;
    int e = (int)(t >> 5), c = (int)(t & 31);
    int a, b;
    if (e < EPT) { a = sp[e];          b = dp[e] + OFF_TR; }
    else { int i = e - EPT; a = st[i] + OFF_TR; b = dt[i] + OFF_AR; }
    float4 va = ((const float4*)(x + (size_t)a * H))[c];
    float4 vb = ((const float4*)(x + (size_t)b * H))[c];
    red4(g_agg + (size_t)b * H + 4 * c, va);
    red4(g_agg + (size_t)a * H + 4 * c, vb);
}

// ---------------- 2D-register-tiled f32x2 GEMM, double-buffered staging ------
// 512 thr / 16 warps (4x4 grid). Block tile 128 nodes x 128 cols, K=KK.
// Warp tile 32x32; lane tile 4 nodes x 8 cols (col-paired f32x2 accumulators).
// WT[k][132] resident (transposed W, [W1;W2] concat when DUAL).
// A chunks (32 k's) pipelined: LDG(chunk kc+1) issued BEFORE compute(chunk kc),
// STS after compute into the alternate Ash buffer -> global latency hidden.
// SCALE: inv[node] folded into A(agg)-part staging.
// GATHER: A rows via lrow/lcol (predictor concat). DOT: Wp2-dot epilogue.
template<int KK, bool DUAL, bool SCALE, bool RELU, bool GATHER, bool DOT>
__global__ void __launch_bounds__(512, 1) k_gemm(
    const float* __restrict__ A, const float* __restrict__ B,
    const float* __restrict__ inv,
    const float* __restrict__ W1, const float* __restrict__ W2,
    const float* __restrict__ b1, const float* __restrict__ b2,
    const int* __restrict__ lrow, const int* __restrict__ lcol,
    const float* __restrict__ wp2, const float* __restrict__ bp2,
    float* __restrict__ out, int n)
{
    extern __shared__ float sm[];
    float* WT   = sm;                     // KK x 132
    float* Ash  = WT + KK * 132;          // 2 x (32 x 132)
    float* bs   = Ash + 2 * 32 * 132;     // 128
    float* w2s  = bs + 128;               // 128
    float* lsum = w2s + 128;              // 128

    const int tid = threadIdx.x;
    constexpr int NC = KK / 32;           // chunks per tile

    // ---- stage WT (transposed weights, once per block) ----
    for (int idx = tid; idx < KK * 32; idx += 512) {
        int c = idx / (KK / 4), kq = idx % (KK / 4);
        const float* src;
        if (DUAL) src = (kq < 32) ? (W1 + c * 128 + kq * 4)
                                  : (W2 + c * 128 + (kq - 32) * 4);
        else      src = W1 + c * KK + kq * 4;
        float4 v = *(const float4*)src;
        WT[(kq * 4 + 0) * 132 + c] = v.x;
        WT[(kq * 4 + 1) * 132 + c] = v.y;
        WT[(kq * 4 + 2) * 132 + c] = v.z;
        WT[(kq * 4 + 3) * 132 + c] = v.w;
    }
    for (int j = tid; j < 128; j += 512) {
        bs[j] = b1[j] + (b2 ? b2[j] : 0.0f);
        if (DOT) w2s[j] = wp2[j];
    }
    __syncthreads();

    const int w  = tid >> 5, jt = tid & 31;
    const int wr = w >> 2,   wc = w & 3;
    const int lr = jt >> 2,  lc = jt & 3;
    const int nodeoff = wr * 32 + lr * 4;
    const int coloff  = wc * 32 + lc * 8;

    const int ntiles = (n + 127) >> 7;
    const int snode = tid & 127, skg = tid >> 7;   // staging: node, k-group(0..3)

    // per-thread chunk load (global -> regs)
    auto ldchunk = [&](int n0, int kc, float4& v0, float4& v1) {
        int gn = n0 + snode;
        v0 = make_float4(0.f, 0.f, 0.f, 0.f); v1 = v0;
        if (gn < n) {
            const float* src;
            if (GATHER) {
                int row = (kc < 4) ? lrow[gn] : (OFF_TR + lcol[gn]);
                src = B + (size_t)row * 128 + (kc & 3) * 32 + skg * 8;
            } else if (DUAL) {
                src = (kc < 4) ? (A + (size_t)gn * 128 + kc * 32 + skg * 8)
                               : (B + (size_t)gn * 128 + (kc - 4) * 32 + skg * 8);
            } else {
                src = A + (size_t)gn * KK + kc * 32 + skg * 8;
            }
            v0 = ((const float4*)src)[0];
            v1 = ((const float4*)src)[1];
            if (SCALE && kc < 4) {
                float s = inv[gn];
                v0.x *= s; v0.y *= s; v0.z *= s; v0.w *= s;
                v1.x *= s; v1.y *= s; v1.z *= s; v1.w *= s;
            }
        }
    };
    // regs -> smem (transposed)
    auto stchunk = [&](int buf, float4 v0, float4 v1) {
        float* ab = Ash + buf * 4224 + (skg * 8) * 132 + snode;
        ab[0 * 132] = v0.x; ab[1 * 132] = v0.y;
        ab[2 * 132] = v0.z; ab[3 * 132] = v0.w;
        ab[4 * 132] = v1.x; ab[5 * 132] = v1.y;
        ab[6 * 132] = v1.z; ab[7 * 132] = v1.w;
    };

    for (int tile = blockIdx.x; tile < ntiles; tile += GRID) {
        const int n0 = tile << 7;

        u64 acc[4][4];
        #pragma unroll
        for (int i = 0; i < 4; i++)
            #pragma unroll
            for (int p = 0; p < 4; p++) acc[i][p] = 0ull;

        if (DOT && tid < 128) lsum[tid] = 0.f;

        // prologue: chunk 0 -> buf 0
        {
            float4 p0, p1;
            ldchunk(n0, 0, p0, p1);
            stchunk(0, p0, p1);
        }
        __syncthreads();

        #pragma unroll 1
        for (int kc = 0; kc < NC; kc++) {
            // prefetch next chunk into registers (latency hidden by compute)
            float4 p0, p1;
            if (kc + 1 < NC) ldchunk(n0, kc + 1, p0, p1);

            const float* Ab = Ash + (kc & 1) * 4224;
            const float* wbase = WT + (size_t)(kc * 32) * 132 + coloff;
            #pragma unroll 4
            for (int kk = 0; kk < 32; kk++) {
                float4 a = *(const float4*)(Ab + kk * 132 + nodeoff);
                const float* wrp = wbase + kk * 132;
                ulonglong2 w01 = *(const ulonglong2*)wrp;
                ulonglong2 w23 = *(const ulonglong2*)(wrp + 4);
                u64 d0 = dup(a.x), d1 = dup(a.y), d2 = dup(a.z), d3 = dup(a.w);
                fma2(acc[0][0], d0, w01.x); fma2(acc[0][1], d0, w01.y);
                fma2(acc[0][2], d0, w23.x); fma2(acc[0][3], d0, w23.y);
                fma2(acc[1][0], d1, w01.x); fma2(acc[1][1], d1, w01.y);
                fma2(acc[1][2], d1, w23.x); fma2(acc[1][3], d1, w23.y);
                fma2(acc[2][0], d2, w01.x); fma2(acc[2][1], d2, w01.y);
                fma2(acc[2][2], d2, w23.x); fma2(acc[2][3], d2, w23.y);
                fma2(acc[3][0], d3, w01.x); fma2(acc[3][1], d3, w01.y);
                fma2(acc[3][2], d3, w23.x); fma2(acc[3][3], d3, w23.y);
            }

            if (kc + 1 < NC) stchunk((kc + 1) & 1, p0, p1);
            __syncthreads();   // STS visible to everyone before next compute
        }

        // ---- epilogue ----
        #pragma unroll
        for (int i = 0; i < 4; i++) {
            int gn = n0 + nodeoff + i;
            U64F2 p0, p1, p2, p3;
            p0.u = acc[i][0]; p1.u = acc[i][1]; p2.u = acc[i][2]; p3.u = acc[i][3];
            float v[8];
            v[0] = p0.f.x + bs[coloff + 0]; v[1] = p0.f.y + bs[coloff + 1];
            v[2] = p1.f.x + bs[coloff + 2]; v[3] = p1.f.y + bs[coloff + 3];
            v[4] = p2.f.x + bs[coloff + 4]; v[5] = p2.f.y + bs[coloff + 5];
            v[6] = p3.f.x + bs[coloff + 6]; v[7] = p3.f.y + bs[coloff + 7];
            if (RELU) {
                #pragma unroll
                for (int j = 0; j < 8; j++) v[j] = fmaxf(v[j], 0.f);
            }
            if (DOT) {
                float part = 0.f;
                #pragma unroll
                for (int j = 0; j < 8; j++) part += v[j] * w2s[coloff + j];
                part += __shfl_xor_sync(0xffffffffu, part, 1);
                part += __shfl_xor_sync(0xffffffffu, part, 2);
                if (lc == 0 && gn < n) atomicAdd(&lsum[nodeoff + i], part);
            } else if (gn < n) {
                *(float4*)(out + (size_t)gn * 128 + coloff)     = make_float4(v[0], v[1], v[2], v[3]);
                *(float4*)(out + (size_t)gn * 128 + coloff + 4) = make_float4(v[4], v[5], v[6], v[7]);
            }
        }
        if (DOT) {
            __syncthreads();
            if (tid < 128) {
                int gn = n0 + tid;
                if (gn < n) out[gn] = lsum[tid] + bp2[0];
            }
        }
    }
}

// ---------------- launch ----------------
extern "C" void kernel_launch(void* const* d_in, const int* in_sizes, int n_in,
                              void* d_out, int out_size)
{
    const int*   pl_ids   = (const int*)  d_in[0];
    const int*   ar_ids   = (const int*)  d_in[1];
    const float* track_x  = (const float*)d_in[2];
    const int*   src_pt   = (const int*)  d_in[3];
    const int*   dst_pt   = (const int*)  d_in[4];
    const int*   src_ta   = (const int*)  d_in[5];
    const int*   dst_ta   = (const int*)  d_in[6];
    const int*   lab_row  = (const int*)  d_in[7];
    const int*   lab_col  = (const int*)  d_in[8];
    const float* pl_table = (const float*)d_in[9];
    const float* ar_table = (const float*)d_in[10];
    const float* Wtr      = (const float*)d_in[11];
    const float* btr      = (const float*)d_in[12];
    const float* type_tab = (const float*)d_in[13];
    const float* Wl0      = (const float*)d_in[14];
    const float* bl0      = (const float*)d_in[15];
    const float* Wr0      = (const float*)d_in[16];
    const float* Wl1      = (const float*)d_in[17];
    const float* bl1      = (const float*)d_in[18];
    const float* Wr1      = (const float*)d_in[19];
    const float* Wp1      = (const float*)d_in[20];
    const float* bp1      = (const float*)d_in[21];
    const float* Wp2      = (const float*)d_in[22];
    const float* bp2      = (const float*)d_in[23];
    float* out = (float*)d_out;

    float *x, *y, *agg, *inv; int* deg;
    cudaGetSymbolAddress((void**)&x,   g_x);
    cudaGetSymbolAddress((void**)&y,   g_y);
    cudaGetSymbolAddress((void**)&agg, g_agg);
    cudaGetSymbolAddress((void**)&inv, g_inv);
    cudaGetSymbolAddress((void**)&deg, g_deg);

    const int SMEM_256 = (256 * 132 + 2 * 32 * 132 + 384) * 4;   // 170496
    const int SMEM_128 = (128 * 132 + 2 * 32 * 132 + 384) * 4;   // 102912

    cudaFuncSetAttribute(k_gemm<128, false, false, false, false, false>, cudaFuncAttributeMaxDynamicSharedMemorySize, SMEM_128);
    cudaFuncSetAttribute(k_gemm<256, true,  true,  true,  false, false>, cudaFuncAttributeMaxDynamicSharedMemorySize, SMEM_256);
    cudaFuncSetAttribute(k_gemm<256, false, false, true,  true,  true >, cudaFuncAttributeMaxDynamicSharedMemorySize, SMEM_256);

    // graph-node order: encode GEMM at node 5 for ncu
    cudaMemsetAsync(deg, 0, (size_t)NT * sizeof(int));                                  // 1
    k_deg<<<(EPT + ETA + 255) / 256, 256>>>(src_pt, dst_pt, src_ta, dst_ta);            // 2
    k_inv<<<(NT + 255) / 256, 256>>>();                                                 // 3
    k_embed2<<<((NPL + NAR) * 32 + 255) / 256, 256>>>(pl_ids, ar_ids, pl_table,         // 4
                                                      ar_table, type_tab, x);
    k_gemm<128, false, false, false, false, false><<<GRID, 512, SMEM_128>>>(            // 5 <- profiled
        track_x, nullptr, nullptr, Wtr, nullptr, btr, type_tab + H,
        nullptr, nullptr, nullptr, nullptr, x + (size_t)OFF_TR * H, NTR);

    const long long sc_threads = (long long)(EPT + ETA) * 32;
    const int sc_blocks = (int)((sc_threads + 255) / 256);

    cudaMemsetAsync(agg, 0, (size_t)NT * H * sizeof(float));                            // 6
    k_scatter<<<sc_blocks, 256>>>(x, src_pt, dst_pt, src_ta, dst_ta);                   // 7
    k_gemm<256, true, true, true, false, false><<<GRID, 512, SMEM_256>>>(               // 8
        agg, x, inv, Wl0, Wr0, bl0, nullptr,
        nullptr, nullptr, nullptr, nullptr, y, NT);

    cudaMemsetAsync(agg, 0, (size_t)NT * H * sizeof(float));                            // 9
    k_scatter<<<sc_blocks, 256>>>(y, src_pt, dst_pt, src_ta, dst_ta);                   // 10
    k_gemm<256, true, true, true, false, false><<<GRID, 512, SMEM_256>>>(               // 11
        agg, y, inv, Wl1, Wr1, bl1, nullptr,
        nullptr, nullptr, nullptr, nullptr, x, NT);

    k_gemm<256, false, false, true, true, true><<<GRID, 512, SMEM_256>>>(               // 12
        nullptr, x, nullptr, Wp1, nullptr, bp1, nullptr,
        lab_row, lab_col, Wp2, bp2, out, LBL);
}

// round 9
// speedup vs baseline: 2.1609x; 1.7430x over previous
#include <cuda_runtime.h>
#include <cuda_bf16.h>
#include <cstddef>
#include <cstdint>

#define H       128
#define NPL     100000
#define NTR     200000
#define NAR     50000
#define NT      350000
#define OFF_TR  100000
#define OFF_AR  300000
#define EPT     500000
#define ETA     200000
#define LBL     100000
#define GRID    152

// ---------------- scratch ----------------
__device__ float g_x  [(size_t)NT * H];
__device__ float g_y  [(size_t)NT * H];
__device__ float g_agg[(size_t)NT * H];
__device__ float g_inv[NT];
__device__ int   g_deg[NT];

// ---------------- generic helpers ----------------
__device__ __forceinline__ void red4(float* p, float4 v) {
    asm volatile("red.global.add.v4.f32 [%0], {%1,%2,%3,%4};"
                 :: "l"(p), "f"(v.x), "f"(v.y), "f"(v.z), "f"(v.w) : "memory");
}
__device__ __forceinline__ uint32_t smem_u32(const void* p) {
    uint32_t a;
    asm("{ .reg .u64 t; cvta.to.shared.u64 t, %1; cvt.u32.u64 %0, t; }" : "=r"(a) : "l"(p));
    return a;
}
#define SWZ(o) ((o) ^ (((o) >> 3) & 0x70))

// ---------------- mma.sync helpers (baseline PTX, assembles for compute_103) --
__device__ __forceinline__ void ldsm4(uint32_t& r0, uint32_t& r1, uint32_t& r2,
                                      uint32_t& r3, uint32_t addr) {
    asm volatile("ldmatrix.sync.aligned.m8n8.x4.shared.b16 {%0,%1,%2,%3}, [%4];"
                 : "=r"(r0), "=r"(r1), "=r"(r2), "=r"(r3) : "r"(addr));
}
__device__ __forceinline__ void mma16816(float* c, uint32_t a0, uint32_t a1,
                                         uint32_t a2, uint32_t a3,
                                         uint32_t b0, uint32_t b1) {
    asm volatile(
        "mma.sync.aligned.m16n8k16.row.col.f32.bf16.bf16.f32 "
        "{%0,%1,%2,%3}, {%4,%5,%6,%7}, {%8,%9}, {%0,%1,%2,%3};"
        : "+f"(c[0]), "+f"(c[1]), "+f"(c[2]), "+f"(c[3])
        : "r"(a0), "r"(a1), "r"(a2), "r"(a3), "r"(b0), "r"(b1));
}

// split fp32 -> (hi, lo) bf16 pairs; 8 elems -> 4+4 packed u32
__device__ __forceinline__ void cvt8(float4 v0, float4 v1, uint32_t* hi, uint32_t* lo) {
    float f[8] = {v0.x, v0.y, v0.z, v0.w, v1.x, v1.y, v1.z, v1.w};
    unsigned short hb[8], lb[8];
    #pragma unroll
    for (int i = 0; i < 8; i++) {
        __nv_bfloat16 h = __float2bfloat16_rn(f[i]);
        hb[i] = __bfloat16_as_ushort(h);
        float l = f[i] - __bfloat162float(h);
        lb[i] = __bfloat16_as_ushort(__float2bfloat16_rn(l));
    }
    #pragma unroll
    for (int j = 0; j < 4; j++) {
        hi[j] = (uint32_t)hb[2 * j] | ((uint32_t)hb[2 * j + 1] << 16);
        lo[j] = (uint32_t)lb[2 * j] | ((uint32_t)lb[2 * j + 1] << 16);
    }
}

// ---------------- small kernels ----------------
__global__ void k_embed2(const int* __restrict__ pl, const int* __restrict__ ar,
                         const float* __restrict__ plt, const float* __restrict__ art,
                         const float* __restrict__ tt, float* __restrict__ x)
{
    int t = blockIdx.x * blockDim.x + threadIdx.x;
    if (t < NPL * 32) {
        int i = t >> 5, c = t & 31;
        float4 v  = ((const float4*)(plt + (size_t)pl[i] * H))[c];
        float4 tv = ((const float4*)tt)[c];
        v.x += tv.x; v.y += tv.y; v.z += tv.z; v.w += tv.w;
        ((float4*)(x + (size_t)i * H))[c] = v;
    } else {
        t -= NPL * 32;
        if (t >= NAR * 32) return;
        int i = t >> 5, c = t & 31;
        float4 v  = ((const float4*)(art + (size_t)ar[i] * H))[c];
        float4 tv = ((const float4*)(tt + 2 * H))[c];
        v.x += tv.x; v.y += tv.y; v.z += tv.z; v.w += tv.w;
        ((float4*)(x + (size_t)(OFF_AR + i) * H))[c] = v;
    }
}

__global__ void k_deg(const int* __restrict__ sp, const int* __restrict__ dp,
                      const int* __restrict__ st, const int* __restrict__ dt)
{
    int e = blockIdx.x * blockDim.x + threadIdx.x;
    if (e < EPT) {
        atomicAdd(&g_deg[dp[e] + OFF_TR], 1);
        atomicAdd(&g_deg[sp[e]], 1);
    } else if (e < EPT + ETA) {
        int i = e - EPT;
        atomicAdd(&g_deg[dt[i] + OFF_AR], 1);
        atomicAdd(&g_deg[st[i] + OFF_TR], 1);
    }
}

__global__ void k_inv()
{
    int i = blockIdx.x * blockDim.x + threadIdx.x;
    if (i < NT) g_inv[i] = 1.0f / fmaxf((float)g_deg[i], 1.0f);
}

__global__ void k_scatter(const float* __restrict__ x,
                          const int* __restrict__ sp, const int* __restrict__ dp,
                          const int* __restrict__ st, const int* __restrict__ dt)
{
    long long t = (long long)blockIdx.x * blockDim.x + threadIdx.x;
    if (t >= (long long)(EPT + ETA) * 32) return;
    int e = (int)(t >> 5), c = (int)(t & 31);
    int a, b;
    if (e < EPT) { a = sp[e];          b = dp[e] + OFF_TR; }
    else { int i = e - EPT; a = st[i] + OFF_TR; b = dt[i] + OFF_AR; }
    float4 va = ((const float4*)(x + (size_t)a * H))[c];
    float4 vb = ((const float4*)(x + (size_t)b * H))[c];
    red4(g_agg + (size_t)b * H + 4 * c, va);
    red4(g_agg + (size_t)a * H + 4 * c, vb);
}

// ---------------- split-bf16 mma.sync GEMM ----------------
// out[n][128] = act( concatK(A*, B) @ Wcat^T + bias ), K = HALVES*128.
// Split x = hi + lo (bf16); products Ah*Wh + Ah*Wl + Al*Wh (lo*lo dropped).
// Tiles: 128 rows x 64 bf16 = 128B rows, SW128-swizzled (ldmatrix-friendly).
// W tiles resident (HALVES*2 chunks x {hi,lo}); A (hi/lo, 2 chunks) per half.
// 16 warps in 4x4 grid; warp = 32 nodes x 32 cols; per k16: 2 A-ldsm4,
// 2 B-ldsm4, 8 mma.m16n8k16. SCALE: inv folded into half-0 staging.
// GATHER: A rows via lrow/lcol. DOT: Wp2 logits epilogue via smem reduce.
template<int HALVES, bool DUALW, bool SCALE, bool RELU, bool GATHER, bool DOT>
__global__ void __launch_bounds__(512, 1) k_mma(
    const float* __restrict__ A, const float* __restrict__ B,
    const float* __restrict__ inv,
    const float* __restrict__ W1, const float* __restrict__ W2,
    const float* __restrict__ b1, const float* __restrict__ b2,
    const int* __restrict__ lrow, const int* __restrict__ lcol,
    const float* __restrict__ wp2, const float* __restrict__ bp2,
    float* __restrict__ out, int n)
{
    extern __shared__ char smraw[];
    const uint32_t raw  = smem_u32(smraw);
    const uint32_t base = (raw + 1023) & ~1023u;
    char* sb = smraw + (base - raw);

    constexpr uint32_t WB   = (uint32_t)HALVES * 4 * 16384;  // W tiles
    constexpr uint32_t AHI  = WB;
    constexpr uint32_t ALO  = WB + 32768;
    constexpr uint32_t SOFF = WB + 65536;
    constexpr int KK = HALVES * 128;

    float* bs   = (float*)(sb + SOFF);
    float* w2s  = (float*)(sb + SOFF + 512);
    float* lsum = (float*)(sb + SOFF + 1024);

    const int tid = threadIdx.x;
    const int wid = tid >> 5, lane = tid & 31;

    // ---- stage W (hi/lo split, SW128 tiles), once per block ----
    for (int it = tid; it < HALVES * 2048; it += 512) {
        int half = it >> 11, rem = it & 2047;
        int row = rem >> 4, kg = rem & 15;
        int kglob = half * 128 + kg * 8;
        const float* src;
        if (DUALW) src = (kglob < 128) ? (W1 + (size_t)row * 128 + kglob)
                                       : (W2 + (size_t)row * 128 + (kglob - 128));
        else       src = W1 + (size_t)row * KK + kglob;
        float4 v0 = ((const float4*)src)[0];
        float4 v1 = ((const float4*)src)[1];
        uint32_t hi[4], lo[4];
        cvt8(v0, v1, hi, lo);
        int chunk = kg >> 3, kgl = kg & 7;
        uint32_t swo = SWZ((uint32_t)(row * 128 + kgl * 16));
        uint32_t thi = (uint32_t)(((half * 2 + chunk) * 2 + 0)) * 16384;
        uint32_t tlo = (uint32_t)(((half * 2 + chunk) * 2 + 1)) * 16384;
        *(uint4*)(sb + thi + swo) = make_uint4(hi[0], hi[1], hi[2], hi[3]);
        *(uint4*)(sb + tlo + swo) = make_uint4(lo[0], lo[1], lo[2], lo[3]);
    }
    for (int j = tid; j < 128; j += 512) {
        bs[j] = b1[j] + (b2 ? b2[j] : 0.0f);
        if (DOT) w2s[j] = wp2[j];
    }
    __syncthreads();

    // warp/lane geometry
    const int wr = wid >> 2, wc = wid & 3;
    const uint32_t rowA  = (uint32_t)(lane & 15);
    const uint32_t kselA = (uint32_t)((lane >> 4) * 16);
    const uint32_t rowB  = (uint32_t)(((lane >> 4) * 8) + (lane & 7));
    const uint32_t kselB = (uint32_t)(((lane >> 3) & 1) * 16);

    const int ntiles = (n + 127) >> 7;

    for (int tile = blockIdx.x; tile < ntiles; tile += GRID) {
        const int n0 = tile << 7;

        float acc[2][4][4];
        #pragma unroll
        for (int mt = 0; mt < 2; mt++)
            #pragma unroll
            for (int nt = 0; nt < 4; nt++)
                #pragma unroll
                for (int q = 0; q < 4; q++) acc[mt][nt][q] = 0.f;

        if (DOT && tid < 128) lsum[tid] = 0.f;

        #pragma unroll
        for (int half = 0; half < HALVES; half++) {
            // ---- stage A (hi/lo) for this half ----
            for (int it = tid; it < 2048; it += 512) {
                int row = it >> 4, kg = it & 15;
                int gn = n0 + row;
                float4 v0 = make_float4(0.f, 0.f, 0.f, 0.f), v1 = v0;
                if (gn < n) {
                    const float* src;
                    if (GATHER) {
                        int r = half ? (OFF_TR + lcol[gn]) : lrow[gn];
                        src = B + (size_t)r * 128 + kg * 8;
                    } else if (HALVES == 2) {
                        src = (half ? B : A) + (size_t)gn * 128 + kg * 8;
                    } else {
                        src = A + (size_t)gn * 128 + kg * 8;
                    }
                    v0 = ((const float4*)src)[0];
                    v1 = ((const float4*)src)[1];
                    if (SCALE && half == 0) {
                        float s = inv[gn];
                        v0.x *= s; v0.y *= s; v0.z *= s; v0.w *= s;
                        v1.x *= s; v1.y *= s; v1.z *= s; v1.w *= s;
                    }
                }
                uint32_t hi[4], lo[4];
                cvt8(v0, v1, hi, lo);
                int chunk = kg >> 3, kgl = kg & 7;
                uint32_t swo = SWZ((uint32_t)(row * 128 + kgl * 16));
                *(uint4*)(sb + AHI + chunk * 16384 + swo) = make_uint4(hi[0], hi[1], hi[2], hi[3]);
                *(uint4*)(sb + ALO + chunk * 16384 + swo) = make_uint4(lo[0], lo[1], lo[2], lo[3]);
            }
            __syncthreads();

            // ---- compute: 2 chunks x 3 split products x 4 k16 steps ----
            #pragma unroll
            for (int cc = 0; cc < 2; cc++) {
                const uint32_t ah = AHI + cc * 16384;
                const uint32_t al = ALO + cc * 16384;
                const uint32_t wh = (uint32_t)(((half * 2 + cc) * 2 + 0)) * 16384;
                const uint32_t wl = (uint32_t)(((half * 2 + cc) * 2 + 1)) * 16384;
                const uint32_t apair[3] = { ah, ah, al };
                const uint32_t wpair[3] = { wh, wl, wh };
                #pragma unroll
                for (int sp = 0; sp < 3; sp++) {
                    const uint32_t ab = base + apair[sp];
                    const uint32_t wb = base + wpair[sp];
                    #pragma unroll
                    for (int s = 0; s < 4; s++) {
                        uint32_t af[2][4];
                        #pragma unroll
                        for (int mt = 0; mt < 2; mt++) {
                            uint32_t off = (uint32_t)((wr * 32 + mt * 16) + rowA) * 128
                                         + (uint32_t)(s * 32) + kselA;
                            ldsm4(af[mt][0], af[mt][1], af[mt][2], af[mt][3], ab + SWZ(off));
                        }
                        uint32_t bf[4][2];
                        #pragma unroll
                        for (int bp = 0; bp < 2; bp++) {
                            uint32_t off = (uint32_t)((wc * 32 + bp * 16) + rowB) * 128
                                         + (uint32_t)(s * 32) + kselB;
                            uint32_t r0, r1, r2, r3;
                            ldsm4(r0, r1, r2, r3, wb + SWZ(off));
                            bf[bp * 2][0] = r0;     bf[bp * 2][1] = r1;
                            bf[bp * 2 + 1][0] = r2; bf[bp * 2 + 1][1] = r3;
                        }
                        #pragma unroll
                        for (int mt = 0; mt < 2; mt++)
                            #pragma unroll
                            for (int nt = 0; nt < 4; nt++)
                                mma16816(acc[mt][nt],
                                         af[mt][0], af[mt][1], af[mt][2], af[mt][3],
                                         bf[nt][0], bf[nt][1]);
                    }
                }
            }
            __syncthreads();   // A smem free before restage / next tile
        }

        // ---- epilogue ----
        const int rbase = wr * 32 + (lane >> 2);
        const int cbase = wc * 32 + 2 * (lane & 3);
        if (DOT) {
            #pragma unroll
            for (int mt = 0; mt < 2; mt++) {
                float plo = 0.f, phi = 0.f;
                #pragma unroll
                for (int nt = 0; nt < 4; nt++) {
                    int col = cbase + nt * 8;
                    float w0 = w2s[col], w1 = w2s[col + 1];
                    float bb0 = bs[col], bb1 = bs[col + 1];
                    plo += fmaxf(acc[mt][nt][0] + bb0, 0.f) * w0
                         + fmaxf(acc[mt][nt][1] + bb1, 0.f) * w1;
                    phi += fmaxf(acc[mt][nt][2] + bb0, 0.f) * w0
                         + fmaxf(acc[mt][nt][3] + bb1, 0.f) * w1;
                }
                plo += __shfl_xor_sync(0xffffffffu, plo, 1);
                plo += __shfl_xor_sync(0xffffffffu, plo, 2);
                phi += __shfl_xor_sync(0xffffffffu, phi, 1);
                phi += __shfl_xor_sync(0xffffffffu, phi, 2);
                if ((lane & 3) == 0) {
                    atomicAdd(&lsum[rbase + mt * 16], plo);
                    atomicAdd(&lsum[rbase + mt * 16 + 8], phi);
                }
            }
            __syncthreads();
            if (tid < 128) {
                int gn = n0 + tid;
                if (gn < n) out[gn] = lsum[tid] + bp2[0];
            }
            __syncthreads();
        } else {
            #pragma unroll
            for (int mt = 0; mt < 2; mt++) {
                int r0 = n0 + rbase + mt * 16;
                int r1 = r0 + 8;
                #pragma unroll
                for (int nt = 0; nt < 4; nt++) {
                    int col = cbase + nt * 8;
                    float bb0 = bs[col], bb1 = bs[col + 1];
                    float2 vlo = make_float2(acc[mt][nt][0] + bb0, acc[mt][nt][1] + bb1);
                    float2 vhi = make_float2(acc[mt][nt][2] + bb0, acc[mt][nt][3] + bb1);
                    if (RELU) {
                        vlo.x = fmaxf(vlo.x, 0.f); vlo.y = fmaxf(vlo.y, 0.f);
                        vhi.x = fmaxf(vhi.x, 0.f); vhi.y = fmaxf(vhi.y, 0.f);
                    }
                    if (r0 < n) *(float2*)(out + (size_t)r0 * 128 + col) = vlo;
                    if (r1 < n) *(float2*)(out + (size_t)r1 * 128 + col) = vhi;
                }
            }
        }
    }
}

// ---------------- launch ----------------
extern "C" void kernel_launch(void* const* d_in, const int* in_sizes, int n_in,
                              void* d_out, int out_size)
{
    const int*   pl_ids   = (const int*)  d_in[0];
    const int*   ar_ids   = (const int*)  d_in[1];
    const float* track_x  = (const float*)d_in[2];
    const int*   src_pt   = (const int*)  d_in[3];
    const int*   dst_pt   = (const int*)  d_in[4];
    const int*   src_ta   = (const int*)  d_in[5];
    const int*   dst_ta   = (const int*)  d_in[6];
    const int*   lab_row  = (const int*)  d_in[7];
    const int*   lab_col  = (const int*)  d_in[8];
    const float* pl_table = (const float*)d_in[9];
    const float* ar_table = (const float*)d_in[10];
    const float* Wtr      = (const float*)d_in[11];
    const float* btr      = (const float*)d_in[12];
    const float* type_tab = (const float*)d_in[13];
    const float* Wl0      = (const float*)d_in[14];
    const float* bl0      = (const float*)d_in[15];
    const float* Wr0      = (const float*)d_in[16];
    const float* Wl1      = (const float*)d_in[17];
    const float* bl1      = (const float*)d_in[18];
    const float* Wr1      = (const float*)d_in[19];
    const float* Wp1      = (const float*)d_in[20];
    const float* bp1      = (const float*)d_in[21];
    const float* Wp2      = (const float*)d_in[22];
    const float* bp2      = (const float*)d_in[23];
    float* out = (float*)d_out;

    float *x, *y, *agg, *inv; int* deg;
    cudaGetSymbolAddress((void**)&x,   g_x);
    cudaGetSymbolAddress((void**)&y,   g_y);
    cudaGetSymbolAddress((void**)&agg, g_agg);
    cudaGetSymbolAddress((void**)&inv, g_inv);
    cudaGetSymbolAddress((void**)&deg, g_deg);

    const int SMEM_H2 = 1024 + 131072 + 65536 + 1536;   // 199168
    const int SMEM_H1 = 1024 + 65536 + 65536 + 1536;    // 133632

    cudaFuncSetAttribute(k_mma<1, false, false, false, false, false>, cudaFuncAttributeMaxDynamicSharedMemorySize, SMEM_H1);
    cudaFuncSetAttribute(k_mma<2, true,  true,  true,  false, false>, cudaFuncAttributeMaxDynamicSharedMemorySize, SMEM_H2);
    cudaFuncSetAttribute(k_mma<2, false, false, true,  true,  true >, cudaFuncAttributeMaxDynamicSharedMemorySize, SMEM_H2);

    // graph-node order: encode mma-GEMM at node 5 for ncu
    cudaMemsetAsync(deg, 0, (size_t)NT * sizeof(int));                                  // 1
    k_deg<<<(EPT + ETA + 255) / 256, 256>>>(src_pt, dst_pt, src_ta, dst_ta);            // 2
    k_inv<<<(NT + 255) / 256, 256>>>();                                                 // 3
    k_embed2<<<((NPL + NAR) * 32 + 255) / 256, 256>>>(pl_ids, ar_ids, pl_table,         // 4
                                                      ar_table, type_tab, x);
    k_mma<1, false, false, false, false, false><<<GRID, 512, SMEM_H1>>>(                // 5 <- profiled
        track_x, nullptr, nullptr, Wtr, nullptr, btr, type_tab + H,
        nullptr, nullptr, nullptr, nullptr, x + (size_t)OFF_TR * H, NTR);

    const long long sc_threads = (long long)(EPT + ETA) * 32;
    const int sc_blocks = (int)((sc_threads + 255) / 256);

    cudaMemsetAsync(agg, 0, (size_t)NT * H * sizeof(float));                            // 6
    k_scatter<<<sc_blocks, 256>>>(x, src_pt, dst_pt, src_ta, dst_ta);                   // 7
    k_mma<2, true, true, true, false, false><<<GRID, 512, SMEM_H2>>>(                   // 8
        agg, x, inv, Wl0, Wr0, bl0, nullptr,
        nullptr, nullptr, nullptr, nullptr, y, NT);

    cudaMemsetAsync(agg, 0, (size_t)NT * H * sizeof(float));                            // 9
    k_scatter<<<sc_blocks, 256>>>(y, src_pt, dst_pt, src_ta, dst_ta);                   // 10
    k_mma<2, true, true, true, false, false><<<GRID, 512, SMEM_H2>>>(                   // 11
        agg, y, inv, Wl1, Wr1, bl1, nullptr,
        nullptr, nullptr, nullptr, nullptr, x, NT);

    k_mma<2, false, false, true, true, true><<<GRID, 512, SMEM_H2>>>(                   // 12
        nullptr, x, nullptr, Wp1, nullptr, bp1, nullptr,
        lab_row, lab_col, Wp2, bp2, out, LBL);
}

// round 10
// speedup vs baseline: 2.3266x; 1.0767x over previous
#include <cuda_runtime.h>
#include <cuda_bf16.h>
#include <cstddef>
#include <cstdint>

#define H       128
#define NPL     100000
#define NTR     200000
#define NAR     50000
#define NT      350000
#define OFF_TR  100000
#define OFF_AR  300000
#define EPT     500000
#define ETA     200000
#define LBL     100000
#define GRID    152

// ---------------- scratch ----------------
__device__ float g_x  [(size_t)NT * H];
__device__ float g_y  [(size_t)NT * H];
__device__ float g_agg[(size_t)NT * H];
__device__ float g_inv[NT];
__device__ int   g_deg[NT];

// ---------------- generic helpers ----------------
__device__ __forceinline__ void red4(float* p, float4 v) {
    asm volatile("red.global.add.v4.f32 [%0], {%1,%2,%3,%4};"
                 :: "l"(p), "f"(v.x), "f"(v.y), "f"(v.z), "f"(v.w) : "memory");
}
__device__ __forceinline__ uint32_t smem_u32(const void* p) {
    uint32_t a;
    asm("{ .reg .u64 t; cvta.to.shared.u64 t, %1; cvt.u32.u64 %0, t; }" : "=r"(a) : "l"(p));
    return a;
}
#define SWZ(o) ((o) ^ (((o) >> 3) & 0x70))

// ---------------- mma.sync helpers ----------------
__device__ __forceinline__ void ldsm4(uint32_t& r0, uint32_t& r1, uint32_t& r2,
                                      uint32_t& r3, uint32_t addr) {
    asm volatile("ldmatrix.sync.aligned.m8n8.x4.shared.b16 {%0,%1,%2,%3}, [%4];"
                 : "=r"(r0), "=r"(r1), "=r"(r2), "=r"(r3) : "r"(addr));
}
__device__ __forceinline__ void mma16816(float* c, uint32_t a0, uint32_t a1,
                                         uint32_t a2, uint32_t a3,
                                         uint32_t b0, uint32_t b1) {
    asm volatile(
        "mma.sync.aligned.m16n8k16.row.col.f32.bf16.bf16.f32 "
        "{%0,%1,%2,%3}, {%4,%5,%6,%7}, {%8,%9}, {%0,%1,%2,%3};"
        : "+f"(c[0]), "+f"(c[1]), "+f"(c[2]), "+f"(c[3])
        : "r"(a0), "r"(a1), "r"(a2), "r"(a3), "r"(b0), "r"(b1));
}

// split fp32 -> (hi, lo) bf16 pairs; 8 elems -> 4+4 packed u32
__device__ __forceinline__ void cvt8(float4 v0, float4 v1, uint32_t* hi, uint32_t* lo) {
    float f[8] = {v0.x, v0.y, v0.z, v0.w, v1.x, v1.y, v1.z, v1.w};
    unsigned short hb[8], lb[8];
    #pragma unroll
    for (int i = 0; i < 8; i++) {
        __nv_bfloat16 h = __float2bfloat16_rn(f[i]);
        hb[i] = __bfloat16_as_ushort(h);
        float l = f[i] - __bfloat162float(h);
        lb[i] = __bfloat16_as_ushort(__float2bfloat16_rn(l));
    }
    #pragma unroll
    for (int j = 0; j < 4; j++) {
        hi[j] = (uint32_t)hb[2 * j] | ((uint32_t)hb[2 * j + 1] << 16);
        lo[j] = (uint32_t)lb[2 * j] | ((uint32_t)lb[2 * j + 1] << 16);
    }
}

// ---------------- small kernels ----------------
__global__ void k_embed2(const int* __restrict__ pl, const int* __restrict__ ar,
                         const float* __restrict__ plt, const float* __restrict__ art,
                         const float* __restrict__ tt, float* __restrict__ x)
{
    int t = blockIdx.x * blockDim.x + threadIdx.x;
    if (t < NPL * 32) {
        int i = t >> 5, c = t & 31;
        float4 v  = ((const float4*)(plt + (size_t)pl[i] * H))[c];
        float4 tv = ((const float4*)tt)[c];
        v.x += tv.x; v.y += tv.y; v.z += tv.z; v.w += tv.w;
        ((float4*)(x + (size_t)i * H))[c] = v;
    } else {
        t -= NPL * 32;
        if (t >= NAR * 32) return;
        int i = t >> 5, c = t & 31;
        float4 v  = ((const float4*)(art + (size_t)ar[i] * H))[c];
        float4 tv = ((const float4*)(tt + 2 * H))[c];
        v.x += tv.x; v.y += tv.y; v.z += tv.z; v.w += tv.w;
        ((float4*)(x + (size_t)(OFF_AR + i) * H))[c] = v;
    }
}

__global__ void k_deg(const int* __restrict__ sp, const int* __restrict__ dp,
                      const int* __restrict__ st, const int* __restrict__ dt)
{
    int e = blockIdx.x * blockDim.x + threadIdx.x;
    if (e < EPT) {
        atomicAdd(&g_deg[dp[e] + OFF_TR], 1);
        atomicAdd(&g_deg[sp[e]], 1);
    } else if (e < EPT + ETA) {
        int i = e - EPT;
        atomicAdd(&g_deg[dt[i] + OFF_AR], 1);
        atomicAdd(&g_deg[st[i] + OFF_TR], 1);
    }
}

__global__ void k_inv()
{
    int i = blockIdx.x * blockDim.x + threadIdx.x;
    if (i < NT) g_inv[i] = 1.0f / fmaxf((float)g_deg[i], 1.0f);
}

__global__ void k_scatter(const float* __restrict__ x,
                          const int* __restrict__ sp, const int* __restrict__ dp,
                          const int* __restrict__ st, const int* __restrict__ dt)
{
    long long t = (long long)blockIdx.x * blockDim.x + threadIdx.x;
    if (t >= (long long)(EPT + ETA) * 32) return;
    int e = (int)(t >> 5), c = (int)(t & 31);
    int a, b;
    if (e < EPT) { a = sp[e];          b = dp[e] + OFF_TR; }
    else { int i = e - EPT; a = st[i] + OFF_TR; b = dt[i] + OFF_AR; }
    float4 va = ((const float4*)(x + (size_t)a * H))[c];
    float4 vb = ((const float4*)(x + (size_t)b * H))[c];
    red4(g_agg + (size_t)b * H + 4 * c, va);
    red4(g_agg + (size_t)a * H + 4 * c, vb);
}

// ---------------- pipelined split-bf16 mma.sync GEMM ----------------
// out[n][128] = act( concatK(A*, B) @ Wcat^T + bias ), K = 64*NCH.
// M=64 node tiles; K processed in 64-wide chunks, A chunk double-buffered:
//   LDG(chunk c+1 -> regs) || compute(chunk c) || cvt8+STS(c+1) ; sync
// Split x = hi+lo bf16; products Ah*Wh + Ah*Wl + Al*Wh per chunk.
// 16 warps in 2x8 grid; warp = 32 nodes x 16 cols; per k16: 3 ldsm4 + 4 mma.
// W tiles resident (NCH x {hi,lo} x 16KB). SCALE: inv folded into chunks 0-1.
// GATHER: A rows via lrow/lcol. DOT: Wp2 logits epilogue via smem reduce.
template<int KK, bool DUALW, bool SCALE, bool RELU, bool GATHER, bool DOT>
__global__ void __launch_bounds__(512, 1) k_mma(
    const float* __restrict__ A, const float* __restrict__ B,
    const float* __restrict__ inv,
    const float* __restrict__ W1, const float* __restrict__ W2,
    const float* __restrict__ b1, const float* __restrict__ b2,
    const int* __restrict__ lrow, const int* __restrict__ lcol,
    const float* __restrict__ wp2, const float* __restrict__ bp2,
    float* __restrict__ out, int n)
{
    extern __shared__ char smraw[];
    const uint32_t raw  = smem_u32(smraw);
    const uint32_t base = (raw + 1023) & ~1023u;
    char* sb = smraw + (base - raw);

    constexpr int NCH = KK / 64;
    constexpr uint32_t AOFF = (uint32_t)NCH * 2 * 16384;   // after W tiles
    constexpr uint32_t SOFF = AOFF + 2 * 16384;            // after A dbl-buf

    float* bs   = (float*)(sb + SOFF);
    float* w2s  = (float*)(sb + SOFF + 512);
    float* lsum = (float*)(sb + SOFF + 1024);

    const int tid = threadIdx.x;
    const int wid = tid >> 5, lane = tid & 31;

    // ---- stage W (hi/lo split, SW128 tiles of 128 rows x 64 k), once ----
    for (int it = tid; it < NCH * 1024; it += 512) {
        int c = it >> 10, rem = it & 1023;
        int row = rem >> 3, kg = rem & 7;
        int kglob = c * 64 + kg * 8;
        const float* src;
        if (DUALW) src = (kglob < 128) ? (W1 + (size_t)row * 128 + kglob)
                                       : (W2 + (size_t)row * 128 + (kglob - 128));
        else       src = W1 + (size_t)row * KK + kglob;
        float4 v0 = ((const float4*)src)[0];
        float4 v1 = ((const float4*)src)[1];
        uint32_t hi[4], lo[4];
        cvt8(v0, v1, hi, lo);
        uint32_t swo = SWZ((uint32_t)(row * 128 + kg * 16));
        *(uint4*)(sb + (c * 2 + 0) * 16384 + swo) = make_uint4(hi[0], hi[1], hi[2], hi[3]);
        *(uint4*)(sb + (c * 2 + 1) * 16384 + swo) = make_uint4(lo[0], lo[1], lo[2], lo[3]);
    }
    for (int j = tid; j < 128; j += 512) {
        bs[j] = b1[j] + (b2 ? b2[j] : 0.0f);
        if (DOT) w2s[j] = wp2[j];
    }
    __syncthreads();

    // warp/lane geometry: 2x8 warp grid, warp tile 32 nodes x 16 cols
    const int wr = wid >> 3, wc = wid & 7;
    const uint32_t rowA  = (uint32_t)(lane & 15);
    const uint32_t kselA = (uint32_t)((lane >> 4) * 16);
    const uint32_t rowB  = (uint32_t)(((lane >> 4) * 8) + (lane & 7));
    const uint32_t kselB = (uint32_t)(((lane >> 3) & 1) * 16);

    // staging geometry: thread -> (row 0..63, kg 0..7)
    const int srow = tid >> 3, skg = tid & 7;

    const int ntiles = (n + 63) >> 6;

    for (int tile = blockIdx.x; tile < ntiles; tile += gridDim.x) {
        const int n0 = tile << 6;

        float acc[2][2][4];
        #pragma unroll
        for (int mt = 0; mt < 2; mt++)
            #pragma unroll
            for (int nt = 0; nt < 2; nt++)
                #pragma unroll
                for (int q = 0; q < 4; q++) acc[mt][nt][q] = 0.f;

        if (DOT && tid < 64) lsum[tid] = 0.f;

        // per-chunk load (global -> regs)
        auto ldreg = [&](int c, float4& v0, float4& v1) {
            int gn = n0 + srow;
            v0 = make_float4(0.f, 0.f, 0.f, 0.f); v1 = v0;
            if (gn < n) {
                const float* src;
                if (GATHER) {
                    int r = (c < 2) ? lrow[gn] : (OFF_TR + lcol[gn]);
                    src = B + (size_t)r * 128 + (c & 1) * 64 + skg * 8;
                } else if (DUALW) {
                    src = (c < 2) ? (A + (size_t)gn * 128 + c * 64 + skg * 8)
                                  : (B + (size_t)gn * 128 + (c - 2) * 64 + skg * 8);
                } else {
                    src = A + (size_t)gn * KK + c * 64 + skg * 8;
                }
                v0 = ((const float4*)src)[0];
                v1 = ((const float4*)src)[1];
                if (SCALE && c < 2) {
                    float s = inv[gn];
                    v0.x *= s; v0.y *= s; v0.z *= s; v0.w *= s;
                    v1.x *= s; v1.y *= s; v1.z *= s; v1.w *= s;
                }
            }
        };
        // regs -> bf16 smem tiles (hi / lo)
        auto stchunk = [&](int buf, float4 v0, float4 v1) {
            uint32_t hi[4], lo[4];
            cvt8(v0, v1, hi, lo);
            uint32_t swo = SWZ((uint32_t)(srow * 128 + skg * 16));
            char* ab = sb + AOFF + buf * 16384;
            *(uint4*)(ab + swo)        = make_uint4(hi[0], hi[1], hi[2], hi[3]);
            *(uint4*)(ab + 8192 + swo) = make_uint4(lo[0], lo[1], lo[2], lo[3]);
        };

        // prologue: chunk 0 -> buf 0
        {
            float4 v0, v1;
            ldreg(0, v0, v1);
            stchunk(0, v0, v1);
        }
        __syncthreads();

        #pragma unroll
        for (int c = 0; c < NCH; c++) {
            float4 p0, p1;
            if (c + 1 < NCH) ldreg(c + 1, p0, p1);

            // compute chunk c: 3 split products x 4 k16 steps
            const uint32_t ahi = base + AOFF + (uint32_t)(c & 1) * 16384;
            const uint32_t alo = ahi + 8192;
            const uint32_t whi = base + (uint32_t)(c * 2 + 0) * 16384;
            const uint32_t wlo = base + (uint32_t)(c * 2 + 1) * 16384;
            const uint32_t apair[3] = { ahi, ahi, alo };
            const uint32_t wpair[3] = { whi, wlo, whi };
            #pragma unroll
            for (int sp = 0; sp < 3; sp++) {
                const uint32_t ab = apair[sp];
                const uint32_t wb = wpair[sp];
                #pragma unroll
                for (int s = 0; s < 4; s++) {
                    uint32_t af[2][4];
                    #pragma unroll
                    for (int mt = 0; mt < 2; mt++) {
                        uint32_t off = (uint32_t)((wr * 32 + mt * 16) + rowA) * 128
                                     + (uint32_t)(s * 32) + kselA;
                        ldsm4(af[mt][0], af[mt][1], af[mt][2], af[mt][3], ab + SWZ(off));
                    }
                    uint32_t r0, r1, r2, r3;
                    {
                        uint32_t off = (uint32_t)((wc * 16) + rowB) * 128
                                     + (uint32_t)(s * 32) + kselB;
                        ldsm4(r0, r1, r2, r3, wb + SWZ(off));
                    }
                    #pragma unroll
                    for (int mt = 0; mt < 2; mt++) {
                        mma16816(acc[mt][0], af[mt][0], af[mt][1], af[mt][2], af[mt][3], r0, r1);
                        mma16816(acc[mt][1], af[mt][0], af[mt][1], af[mt][2], af[mt][3], r2, r3);
                    }
                }
            }

            if (c + 1 < NCH) stchunk((c + 1) & 1, p0, p1);
            __syncthreads();
        }

        // ---- epilogue ----
        const int grow = lane >> 2;
        const int gcol = (lane & 3) * 2;
        if (DOT) {
            #pragma unroll
            for (int mt = 0; mt < 2; mt++) {
                float plo = 0.f, phi = 0.f;
                #pragma unroll
                for (int nt = 0; nt < 2; nt++) {
                    int col = wc * 16 + nt * 8 + gcol;
                    float w0 = w2s[col], w1 = w2s[col + 1];
                    float bb0 = bs[col], bb1 = bs[col + 1];
                    plo += fmaxf(acc[mt][nt][0] + bb0, 0.f) * w0
                         + fmaxf(acc[mt][nt][1] + bb1, 0.f) * w1;
                    phi += fmaxf(acc[mt][nt][2] + bb0, 0.f) * w0
                         + fmaxf(acc[mt][nt][3] + bb1, 0.f) * w1;
                }
                plo += __shfl_xor_sync(0xffffffffu, plo, 1);
                plo += __shfl_xor_sync(0xffffffffu, plo, 2);
                phi += __shfl_xor_sync(0xffffffffu, phi, 1);
                phi += __shfl_xor_sync(0xffffffffu, phi, 2);
                if ((lane & 3) == 0) {
                    atomicAdd(&lsum[wr * 32 + mt * 16 + grow], plo);
                    atomicAdd(&lsum[wr * 32 + mt * 16 + grow + 8], phi);
                }
            }
            __syncthreads();
            if (tid < 64) {
                int gn = n0 + tid;
                if (gn < n) out[gn] = lsum[tid] + bp2[0];
            }
            __syncthreads();
        } else {
            #pragma unroll
            for (int mt = 0; mt < 2; mt++) {
                int r0 = n0 + wr * 32 + mt * 16 + grow;
                int r1 = r0 + 8;
                #pragma unroll
                for (int nt = 0; nt < 2; nt++) {
                    int col = wc * 16 + nt * 8 + gcol;
                    float bb0 = bs[col], bb1 = bs[col + 1];
                    float2 vlo = make_float2(acc[mt][nt][0] + bb0, acc[mt][nt][1] + bb1);
                    float2 vhi = make_float2(acc[mt][nt][2] + bb0, acc[mt][nt][3] + bb1);
                    if (RELU) {
                        vlo.x = fmaxf(vlo.x, 0.f); vlo.y = fmaxf(vlo.y, 0.f);
                        vhi.x = fmaxf(vhi.x, 0.f); vhi.y = fmaxf(vhi.y, 0.f);
                    }
                    if (r0 < n) *(float2*)(out + (size_t)r0 * 128 + col) = vlo;
                    if (r1 < n) *(float2*)(out + (size_t)r1 * 128 + col) = vhi;
                }
            }
        }
    }
}

// ---------------- launch ----------------
extern "C" void kernel_launch(void* const* d_in, const int* in_sizes, int n_in,
                              void* d_out, int out_size)
{
    const int*   pl_ids   = (const int*)  d_in[0];
    const int*   ar_ids   = (const int*)  d_in[1];
    const float* track_x  = (const float*)d_in[2];
    const int*   src_pt   = (const int*)  d_in[3];
    const int*   dst_pt   = (const int*)  d_in[4];
    const int*   src_ta   = (const int*)  d_in[5];
    const int*   dst_ta   = (const int*)  d_in[6];
    const int*   lab_row  = (const int*)  d_in[7];
    const int*   lab_col  = (const int*)  d_in[8];
    const float* pl_table = (const float*)d_in[9];
    const float* ar_table = (const float*)d_in[10];
    const float* Wtr      = (const float*)d_in[11];
    const float* btr      = (const float*)d_in[12];
    const float* type_tab = (const float*)d_in[13];
    const float* Wl0      = (const float*)d_in[14];
    const float* bl0      = (const float*)d_in[15];
    const float* Wr0      = (const float*)d_in[16];
    const float* Wl1      = (const float*)d_in[17];
    const float* bl1      = (const float*)d_in[18];
    const float* Wr1      = (const float*)d_in[19];
    const float* Wp1      = (const float*)d_in[20];
    const float* bp1      = (const float*)d_in[21];
    const float* Wp2      = (const float*)d_in[22];
    const float* bp2      = (const float*)d_in[23];
    float* out = (float*)d_out;

    float *x, *y, *agg, *inv; int* deg;
    cudaGetSymbolAddress((void**)&x,   g_x);
    cudaGetSymbolAddress((void**)&y,   g_y);
    cudaGetSymbolAddress((void**)&agg, g_agg);
    cudaGetSymbolAddress((void**)&inv, g_inv);
    cudaGetSymbolAddress((void**)&deg, g_deg);

    const int SMEM_K256 = 1024 + 8 * 16384 + 2 * 16384 + 1536;   // 166912
    const int SMEM_K128 = 1024 + 4 * 16384 + 2 * 16384 + 1536;   // 101376

    cudaFuncSetAttribute(k_mma<128, false, false, false, false, false>, cudaFuncAttributeMaxDynamicSharedMemorySize, SMEM_K128);
    cudaFuncSetAttribute(k_mma<256, true,  true,  true,  false, false>, cudaFuncAttributeMaxDynamicSharedMemorySize, SMEM_K256);
    cudaFuncSetAttribute(k_mma<256, false, false, true,  true,  true >, cudaFuncAttributeMaxDynamicSharedMemorySize, SMEM_K256);

    // graph-node order: encode mma-GEMM at node 5 for ncu
    cudaMemsetAsync(deg, 0, (size_t)NT * sizeof(int));                                  // 1
    k_deg<<<(EPT + ETA + 255) / 256, 256>>>(src_pt, dst_pt, src_ta, dst_ta);            // 2
    k_inv<<<(NT + 255) / 256, 256>>>();                                                 // 3
    k_embed2<<<((NPL + NAR) * 32 + 255) / 256, 256>>>(pl_ids, ar_ids, pl_table,         // 4
                                                      ar_table, type_tab, x);
    k_mma<128, false, false, false, false, false><<<GRID, 512, SMEM_K128>>>(            // 5 <- profiled
        track_x, nullptr, nullptr, Wtr, nullptr, btr, type_tab + H,
        nullptr, nullptr, nullptr, nullptr, x + (size_t)OFF_TR * H, NTR);

    const long long sc_threads = (long long)(EPT + ETA) * 32;
    const int sc_blocks = (int)((sc_threads + 255) / 256);

    cudaMemsetAsync(agg, 0, (size_t)NT * H * sizeof(float));                            // 6
    k_scatter<<<sc_blocks, 256>>>(x, src_pt, dst_pt, src_ta, dst_ta);                   // 7
    k_mma<256, true, true, true, false, false><<<GRID, 512, SMEM_K256>>>(               // 8
        agg, x, inv, Wl0, Wr0, bl0, nullptr,
        nullptr, nullptr, nullptr, nullptr, y, NT);

    cudaMemsetAsync(agg, 0, (size_t)NT * H * sizeof(float));                            // 9
    k_scatter<<<sc_blocks, 256>>>(y, src_pt, dst_pt, src_ta, dst_ta);                   // 10
    k_mma<256, true, true, true, false, false><<<GRID, 512, SMEM_K256>>>(               // 11
        agg, y, inv, Wl1, Wr1, bl1, nullptr,
        nullptr, nullptr, nullptr, nullptr, x, NT);

    k_mma<256, false, false, true, true, true><<<GRID, 512, SMEM_K256>>>(               // 12
        nullptr, x, nullptr, Wp1, nullptr, bp1, nullptr,
        lab_row, lab_col, Wp2, bp2, out, LBL);
}